// round 10
// baseline (speedup 1.0000x reference)
#include <cuda_runtime.h>
#include <cuda_bf16.h>
#include <math.h>
#include <stdint.h>

// Problem constants (fixed by setup_inputs)
#define B_   64
#define S_   8
#define DK_  64
#define DA_  2048
#define N_   100000
#define KTOT 512        // S_*DK_
#define KMAX 32
#define NT   782        // n-tiles of 128
#define CAP  1024       // candidate buffer per (b, quarter) (smem)
#define NSPL 4          // tail split factor per b
#define DELTA 4e-3f     // threshold safety margin (>> bf16 score noise)
#define EPSF 1e-8f

// smem layout for k_mma (bytes)
#define STG_STRIDE 288            // 256B fp32 row + split-pad (conflict-free)
#define STG_BUF (128 * STG_STRIDE)   // 36864
#define SM_STG 0                     // 2 bufs: 73728
#define KSROW 144                    // bf16 row: 128B + 16 pad
#define KSBUF (128 * KSROW)          // 18432
#define SM_KS  (2 * STG_BUF)         // 73728; 2 bufs: 36864
#define SM_TOTAL (SM_KS + 2 * KSBUF) // 110592 (108 KB) -> 2 CTAs/SM

// ---------------- device scratch ----------------
__device__ float g_qpart[16 * B_ * KTOT];
__device__ float g_qhat[B_ * KTOT];               // fp32 q̂ (exact rescore)
__device__ uint4 g_qfrag[128 * 32];               // mma A fragments (64 KB)
__device__ float g_s[(size_t)B_ * N_];            // approx scores [b][n]
__device__ float g_rsp[B_ * NT];                  // rsum partials per (b,tile)
__device__ float g_bmax[B_ * NT];                 // per-(b,tile) max
__device__ unsigned long long g_part[B_ * NSPL * KMAX]; // partial top-32s
__device__ int g_done[B_];                        // last-block counters

// ================= helpers =================
__device__ __forceinline__ uint32_t smem_u32(const void* p) {
    uint32_t a;
    asm("{ .reg .u64 t; cvta.to.shared.u64 t, %1; cvt.u32.u64 %0, t; }" : "=r"(a) : "l"(p));
    return a;
}
__device__ __forceinline__ void cp_async16(uint32_t dst, const void* src) {
    asm volatile("cp.async.cg.shared.global [%0], [%1], 16;" :: "r"(dst), "l"(src));
}
#define CP_COMMIT() asm volatile("cp.async.commit_group;" ::: "memory")
#define CP_WAIT1()  asm volatile("cp.async.wait_group 1;" ::: "memory")
__device__ __forceinline__ void ldsm_x4(uint32_t& r0, uint32_t& r1, uint32_t& r2,
                                        uint32_t& r3, uint32_t addr) {
    asm volatile("ldmatrix.sync.aligned.m8n8.x4.shared.b16 {%0,%1,%2,%3}, [%4];"
                 : "=r"(r0), "=r"(r1), "=r"(r2), "=r"(r3) : "r"(addr));
}
__device__ __forceinline__ void mma16816(float* c, const uint32_t* a,
                                         uint32_t b0, uint32_t b1) {
    asm volatile(
        "mma.sync.aligned.m16n8k16.row.col.f32.bf16.bf16.f32 "
        "{%0,%1,%2,%3}, {%4,%5,%6,%7}, {%8,%9}, {%0,%1,%2,%3};"
        : "+f"(c[0]), "+f"(c[1]), "+f"(c[2]), "+f"(c[3])
        : "r"(a[0]), "r"(a[1]), "r"(a[2]), "r"(a[3]), "r"(b0), "r"(b1));
}
__device__ __forceinline__ unsigned flipf(float f) {
    unsigned u = __float_as_uint(f);
    return (u & 0x80000000u) ? ~u : (u | 0x80000000u);
}
__device__ __forceinline__ float unflipf(unsigned u) {
    return __uint_as_float((u & 0x80000000u) ? (u & 0x7FFFFFFFu) : ~u);
}
// 0-MUFU sigmoid(lambda(s-tau)) * exp(s) approximation (rsum only; ~0.1% acc)
__device__ __forceinline__ float rsum_term(float s, float lambda, float tau) {
    float e = 1.f + s * (1.f + s * (0.5f + s * (0.16666667f + s * (0.041666667f + s * 0.0083333333f))));
    float x = lambda * (s - tau);
    float ax = fabsf(x);
    float t;
    if (ax >= 4.5f) {
        t = 1.f;
    } else {
        float y = 0.5f * ax, y2 = y * y;
        float num = y * (27.f + y2);
        float den = fmaf(9.f, y2, 27.f);
        float rc = fmaf(den, -5.10e-4f, 0.05081f);
        rc = rc * (2.f - den * rc);
        rc = rc * (2.f - den * rc);
        t = fminf(num * rc, 1.f);
    }
    float g = fmaf(copysignf(t, x), 0.5f, 0.5f);
    return g * e;
}

// ---------------- K1a: query projection partial GEMM ----------------
__global__ void __launch_bounds__(256) k_proj_partial(const float* __restrict__ z,
                                                      const float* __restrict__ wq) {
    __shared__ float zt[64][33];
    __shared__ float wt[64][33];
    int tid = threadIdx.x;
    int tx = tid & 15, ty = tid >> 4;
    int a_base = blockIdx.x * 128;
    int sk_base = blockIdx.y * 64;
    float acc[4][4] = {};
    for (int t = 0; t < 4; t++) {
        int a0 = a_base + t * 32;
        for (int idx = tid; idx < 64 * 32; idx += 256) {
            int r = idx >> 5, c = idx & 31;
            zt[r][c] = z[r * DA_ + a0 + c];
            wt[r][c] = wq[(size_t)(sk_base + r) * DA_ + a0 + c];
        }
        __syncthreads();
#pragma unroll
        for (int a = 0; a < 32; a++) {
            float zv[4], wv[4];
#pragma unroll
            for (int i = 0; i < 4; i++) zv[i] = zt[4 * ty + i][a];
#pragma unroll
            for (int j = 0; j < 4; j++) wv[j] = wt[4 * tx + j][a];
#pragma unroll
            for (int i = 0; i < 4; i++)
#pragma unroll
                for (int j = 0; j < 4; j++) acc[i][j] += zv[i] * wv[j];
        }
        __syncthreads();
    }
#pragma unroll
    for (int i = 0; i < 4; i++)
#pragma unroll
        for (int j = 0; j < 4; j++)
            g_qpart[blockIdx.x * (B_ * KTOT) + (4 * ty + i) * KTOT + sk_base + 4 * tx + j] = acc[i][j];
}

// ---------------- K1b: reduce + normalize + softmax + emit fragments -------
__global__ void __launch_bounds__(256) k_qfinish(const float* __restrict__ aw) {
    __shared__ __nv_bfloat16 shq[8][64];
    int b = blockIdx.x;
    int tid = threadIdx.x;
    int s = tid >> 5, lane = tid & 31;
    int idx0 = b * KTOT + s * 64 + lane;
    int idx1 = idx0 + 32;
    if (tid == 0) g_done[b] = 0;     // reset last-block counter each call

    float q0 = 0.f, q1 = 0.f;
#pragma unroll
    for (int p = 0; p < 16; p++) {
        q0 += g_qpart[p * (B_ * KTOT) + idx0];
        q1 += g_qpart[p * (B_ * KTOT) + idx1];
    }
    float ss = q0 * q0 + q1 * q1;
#pragma unroll
    for (int off = 16; off > 0; off >>= 1) ss += __shfl_xor_sync(0xFFFFFFFFu, ss, off);
    float m = aw[0];
#pragma unroll
    for (int i = 1; i < 8; i++) m = fmaxf(m, aw[i]);
    float den = 0.f, es = 0.f;
#pragma unroll
    for (int i = 0; i < 8; i++) {
        float e = expf(aw[i] - m);
        den += e;
        if (i == s) es = e;
    }
    float scale = (es / den) / (sqrtf(ss) + EPSF);
    float h0 = q0 * scale, h1 = q1 * scale;
    g_qhat[idx0] = h0;
    g_qhat[idx1] = h1;
    shq[s][lane] = __float2bfloat16(h0);
    shq[s][lane + 32] = __float2bfloat16(h1);
    __syncwarp();

    int kc = lane >> 3, t = (lane >> 1) & 3, h = lane & 1;
    int col = kc * 16 + h * 8 + 2 * t;
    __nv_bfloat162 pr = __halves2bfloat162(*(__nv_bfloat16*)&shq[s][col],
                                           *(__nv_bfloat16*)&shq[s][col + 1]);
    uint32_t val = *reinterpret_cast<uint32_t*>(&pr);
    int gp = b & 15;
    int frag = (s * 4 + kc) * 4 + (b >> 4);
    int comp = 2 * h + (gp >= 8 ? 1 : 0);
    int lanep = (gp & 7) * 4 + t;
    reinterpret_cast<uint32_t*>(g_qfrag)[frag * 128 + lanep * 4 + comp] = val;
}

// ---------------- K2: bf16 HMMA score GEMM, cp.async depth-2 pipeline ------
__global__ void __launch_bounds__(256, 2) k_mma(const float* __restrict__ keys,
                                                const float* __restrict__ tau_p,
                                                const float* __restrict__ lam_p) {
    extern __shared__ char smem[];
    __shared__ float s_rs[2][64];
    __shared__ float s_bm[2][64];
    uint32_t sb = smem_u32(smem);
    int tid = threadIdx.x;
    int wid = tid >> 5, lane = tid & 31;
    int wb = wid & 3, wn = wid >> 2;
    int n0 = blockIdx.x * 128;

    int r = tid >> 1, hf = tid & 1;
    int nrow = n0 + r;
    if (nrow >= N_) nrow = N_ - 1;
    const float* krow0 = keys + (size_t)nrow * DK_ + hf * 32;
    uint32_t mystg = sb + SM_STG + r * STG_STRIDE + hf * 144;

#pragma unroll
    for (int c = 0; c < 8; c++) cp_async16(mystg + c * 16, krow0 + c * 4);
    CP_COMMIT();
#pragma unroll
    for (int c = 0; c < 8; c++)
        cp_async16(mystg + STG_BUF + c * 16, krow0 + (size_t)N_ * DK_ + c * 4);
    CP_COMMIT();

    float acc[8][4] = {};
    int b_rowlane = wn * 64 + (lane & 7);
    int b_kof = (lane >> 3) * 8;

    for (int s = 0; s < S_; s++) {
        uint32_t stg = (s & 1) * STG_BUF;
        CP_WAIT1();
        __syncthreads();

        float4 v[8];
        const float4* sp = reinterpret_cast<const float4*>(smem + stg + r * STG_STRIDE + hf * 144);
#pragma unroll
        for (int j = 0; j < 8; j++) v[j] = sp[j];
        float ssv = 0.f;
#pragma unroll
        for (int j = 0; j < 8; j++)
            ssv += v[j].x * v[j].x + v[j].y * v[j].y + v[j].z * v[j].z + v[j].w * v[j].w;
        ssv += __shfl_xor_sync(0xFFFFFFFFu, ssv, 1);
        float inv = rsqrtf(ssv);

        char* rowp = smem + SM_KS + (s & 1) * KSBUF + r * KSROW + hf * 64;
#pragma unroll
        for (int j = 0; j < 4; j++) {
            float4 a = v[2 * j], b4 = v[2 * j + 1];
            __nv_bfloat162 p0 = __float22bfloat162_rn(make_float2(a.x * inv, a.y * inv));
            __nv_bfloat162 p1 = __float22bfloat162_rn(make_float2(a.z * inv, a.w * inv));
            __nv_bfloat162 p2 = __float22bfloat162_rn(make_float2(b4.x * inv, b4.y * inv));
            __nv_bfloat162 p3 = __float22bfloat162_rn(make_float2(b4.z * inv, b4.w * inv));
            uint4 pk;
            pk.x = *reinterpret_cast<uint32_t*>(&p0);
            pk.y = *reinterpret_cast<uint32_t*>(&p1);
            pk.z = *reinterpret_cast<uint32_t*>(&p2);
            pk.w = *reinterpret_cast<uint32_t*>(&p3);
            *reinterpret_cast<uint4*>(rowp + j * 16) = pk;
        }
        __syncthreads();

        if (s + 2 < S_) {
            const float* src = krow0 + (size_t)(s + 2) * N_ * DK_;
#pragma unroll
            for (int c = 0; c < 8; c++) cp_async16(mystg + stg + c * 16, src + c * 4);
        }
        CP_COMMIT();

        uint32_t afr[4][4];
#pragma unroll
        for (int kc = 0; kc < 4; kc++) {
            uint4 qf = __ldg(&g_qfrag[((s * 4 + kc) * 4 + wb) * 32 + lane]);
            afr[kc][0] = qf.x; afr[kc][1] = qf.y; afr[kc][2] = qf.z; afr[kc][3] = qf.w;
        }
        uint32_t bufo = SM_KS + (s & 1) * KSBUF;
#pragma unroll
        for (int ng = 0; ng < 8; ng++) {
            uint32_t baddr = sb + bufo + (b_rowlane + ng * 8) * KSROW + b_kof * 2;
            uint32_t bb[8];
            ldsm_x4(bb[0], bb[1], bb[2], bb[3], baddr);
            ldsm_x4(bb[4], bb[5], bb[6], bb[7], baddr + 64);
#pragma unroll
            for (int kc = 0; kc < 4; kc++)
                mma16816(acc[ng], afr[kc], bb[kc * 2], bb[kc * 2 + 1]);
        }
    }

    float lambda = __ldg(lam_p), tau = __ldg(tau_p);
    int brow = wb * 16 + (lane >> 2);
    int ncol0 = n0 + wn * 64 + 2 * (lane & 3);
    float rs0 = 0.f, rs1 = 0.f, bm0 = -1e30f, bm1 = -1e30f;
#pragma unroll
    for (int ng = 0; ng < 8; ng++) {
        int n = ncol0 + ng * 8;
        if (n < N_) {
            *reinterpret_cast<float2*>(&g_s[(size_t)brow * N_ + n]) =
                make_float2(acc[ng][0], acc[ng][1]);
            *reinterpret_cast<float2*>(&g_s[(size_t)(brow + 8) * N_ + n]) =
                make_float2(acc[ng][2], acc[ng][3]);
            rs0 += rsum_term(acc[ng][0], lambda, tau) + rsum_term(acc[ng][1], lambda, tau);
            rs1 += rsum_term(acc[ng][2], lambda, tau) + rsum_term(acc[ng][3], lambda, tau);
            bm0 = fmaxf(bm0, fmaxf(acc[ng][0], acc[ng][1]));
            bm1 = fmaxf(bm1, fmaxf(acc[ng][2], acc[ng][3]));
        }
    }
#pragma unroll
    for (int off = 1; off <= 2; off <<= 1) {
        rs0 += __shfl_xor_sync(0xFFFFFFFFu, rs0, off);
        rs1 += __shfl_xor_sync(0xFFFFFFFFu, rs1, off);
        bm0 = fmaxf(bm0, __shfl_xor_sync(0xFFFFFFFFu, bm0, off));
        bm1 = fmaxf(bm1, __shfl_xor_sync(0xFFFFFFFFu, bm1, off));
    }
    if ((lane & 3) == 0) {
        s_rs[wn][brow] = rs0; s_rs[wn][brow + 8] = rs1;
        s_bm[wn][brow] = bm0; s_bm[wn][brow + 8] = bm1;
    }
    __syncthreads();
    if (tid < 64) {
        g_rsp[tid * NT + blockIdx.x] = s_rs[0][tid] + s_rs[1][tid];
        g_bmax[tid * NT + blockIdx.x] = fmaxf(s_bm[0][tid], s_bm[1][tid]);
    }
}

// ---------------- K3: split tail — 4 blocks per b + last-block merge -------
__global__ void __launch_bounds__(256) k_tail(const float* __restrict__ keys,
                                              const float* __restrict__ tau_p,
                                              const float* __restrict__ lam_p,
                                              const int* __restrict__ warm_p,
                                              int has_warm,
                                              float* __restrict__ out,
                                              int out_size) {
    __shared__ unsigned long long cand[CAP];       // 8 KB
    __shared__ unsigned long long w32[8][32];
    __shared__ float sbm[NT];                      // tile maxima (3.1 KB)
    __shared__ int s_tiles[256];
    __shared__ int s_cnt, s_ntile, s_ncand, s_last;
    int bx = blockIdx.x;                           // quarter 0..3
    int b = blockIdx.y;
    int tid = threadIdx.x;
    int wid = tid >> 5, lane = tid & 31;

    // stage tile maxima into smem
    for (int i = tid; i < NT; i += 256) sbm[i] = g_bmax[b * NT + i];
    if (tid == 0) { s_ntile = 0; s_ncand = 0; }
    __syncthreads();

    // bisection: largest lo with count(sbm >= lo) >= 32 (scores in [-1.1, 1.1])
    float lo = -1.1f, hi = 1.1f;
    for (int it = 0; it < 22; it++) {
        float mid = 0.5f * (lo + hi);
        if (tid == 0) s_cnt = 0;
        __syncthreads();
        int c = 0;
        for (int i = tid; i < NT; i += 256) c += (sbm[i] >= mid);
#pragma unroll
        for (int off = 16; off > 0; off >>= 1) c += __shfl_xor_sync(0xFFFFFFFFu, c, off);
        if (lane == 0 && c) atomicAdd(&s_cnt, c);
        __syncthreads();
        if (s_cnt >= KMAX) lo = mid; else hi = mid;
        __syncthreads();
    }
    float T = lo - DELTA;

    // qualifying tile list, this block's quarter only (i % 4 == bx)
    for (int i = bx + 4 * tid; i < NT; i += 1024)
        if (sbm[i] >= T) {
            int k = atomicAdd(&s_ntile, 1);
            if (k < 256) s_tiles[k] = i;
        }
    __syncthreads();
    int ntile = min(s_ntile, 256);

    // collect candidates >= T from qualifying tiles (float4 loads)
    const float* srow = g_s + (size_t)b * N_;
    int total = ntile * 128;
    for (int base = tid * 4; base < total; base += 1024) {
        int tile = s_tiles[base >> 7];
        int n = tile * 128 + (base & 127);
        if (n + 3 < N_) {
            float4 v = *reinterpret_cast<const float4*>(srow + n);
            float sv[4] = {v.x, v.y, v.z, v.w};
#pragma unroll
            for (int j = 0; j < 4; j++) {
                if (sv[j] >= T) {
                    int idx = atomicAdd(&s_ncand, 1);
                    if (idx < CAP)
                        cand[idx] = ((unsigned long long)flipf(sv[j]) << 32) |
                                    (unsigned long long)(0xFFFFFFFFu - (unsigned)(n + j));
                }
            }
        } else {
#pragma unroll
            for (int j = 0; j < 4; j++) {
                int nn = n + j;
                if (nn < N_) {
                    float sv = srow[nn];
                    if (sv >= T) {
                        int idx = atomicAdd(&s_ncand, 1);
                        if (idx < CAP)
                            cand[idx] = ((unsigned long long)flipf(sv) << 32) |
                                        (unsigned long long)(0xFFFFFFFFu - (unsigned)nn);
                    }
                }
            }
        }
    }
    __syncthreads();
    int cnt = min(s_ncand, CAP);

    // exact fp32 rescore in place
    for (int ci = tid; ci < cnt; ci += 256) {
        unsigned n = 0xFFFFFFFFu - (unsigned)(cand[ci] & 0xFFFFFFFFu);
        float stot = 0.f;
#pragma unroll
        for (int s = 0; s < S_; s++) {
            const float4* kp = reinterpret_cast<const float4*>(keys + ((size_t)s * N_ + n) * DK_);
            const float4* qp = reinterpret_cast<const float4*>(g_qhat + b * KTOT + s * 64);
            float ss = 0.f, dt = 0.f;
#pragma unroll
            for (int j = 0; j < 16; j++) {
                float4 kv = __ldg(kp + j);
                float4 qv = qp[j];
                ss += kv.x * kv.x + kv.y * kv.y + kv.z * kv.z + kv.w * kv.w;
                dt += kv.x * qv.x + kv.y * qv.y + kv.z * qv.z + kv.w * qv.w;
            }
            stot += dt / (sqrtf(ss) + EPSF);
        }
        cand[ci] = ((unsigned long long)flipf(stot) << 32) |
                   (unsigned long long)(0xFFFFFFFFu - n);
    }
    __syncthreads();

    // per-warp top-32 over strided slice of exact candidates
    unsigned long long list = 0ull;
    for (int base = wid * 32; base < cnt; base += 256) {
        int ci = base + lane;
        unsigned long long key = (ci < cnt) ? cand[ci] : 0ull;
        unsigned long long cm = __shfl_sync(0xFFFFFFFFu, list, 0);
        unsigned m = __ballot_sync(0xFFFFFFFFu, key > cm);
        while (m) {
            int src = __ffs(m) - 1;
            unsigned long long kk = __shfl_sync(0xFFFFFFFFu, key, src);
            cm = __shfl_sync(0xFFFFFFFFu, list, 0);
            if (kk > cm) {
                unsigned lt = __ballot_sync(0xFFFFFFFFu, list < kk);
                int pos = __popc(lt);
                unsigned long long dn = __shfl_down_sync(0xFFFFFFFFu, list, 1);
                if (lane < pos - 1) list = dn;
                else if (lane == pos - 1) list = kk;
            }
            m &= m - 1;
        }
    }
    w32[wid][lane] = list;
    __syncthreads();

    // warp 0: extract this block's sorted top-32 partial -> global
    if (wid == 0) {
        unsigned long long cc[8];
#pragma unroll
        for (int i = 0; i < 8; i++) cc[i] = w32[i][lane];
        for (int round = 0; round < 32; round++) {
            unsigned long long lm = cc[0];
#pragma unroll
            for (int i = 1; i < 8; i++) lm = (cc[i] > lm) ? cc[i] : lm;
            unsigned long long mm = lm;
#pragma unroll
            for (int off = 16; off > 0; off >>= 1) {
                unsigned long long o = __shfl_xor_sync(0xFFFFFFFFu, mm, off);
                if (o > mm) mm = o;
            }
            unsigned has = __ballot_sync(0xFFFFFFFFu, lm == mm);
            int src = __ffs(has) - 1;
            if (lane == src) {
#pragma unroll
                for (int i = 0; i < 8; i++)
                    if (cc[i] == mm) cc[i] = 0ull;
            }
            if (lane == round)
                g_part[(b * NSPL + bx) * KMAX + round] = mm;
        }
    }

    // last block for this b merges all partials and finishes
    __syncthreads();
    if (tid == 0) {
        __threadfence();
        int old = atomicAdd(&g_done[b], 1);
        s_last = (old == NSPL - 1);
    }
    __syncthreads();
    if (!s_last) return;
    __threadfence();

    // rsum reduction (all 256 threads)
    __shared__ float s_rs[8];
    float rsum = 0.f;
    for (int i = tid; i < NT; i += 256) rsum += g_rsp[b * NT + i];
#pragma unroll
    for (int off = 16; off > 0; off >>= 1) rsum += __shfl_xor_sync(0xFFFFFFFFu, rsum, off);
    if (lane == 0) s_rs[wid] = rsum;
    __syncthreads();

    if (wid == 0) {
        float lambda = __ldg(lam_p), tau = __ldg(tau_p);
        unsigned long long cc[NSPL];
#pragma unroll
        for (int i = 0; i < NSPL; i++)
            cc[i] = g_part[(b * NSPL + i) * KMAX + lane];

        float myS = 0.f;
        int myN = 0;
        for (int round = 0; round < 32; round++) {
            unsigned long long lm = cc[0];
#pragma unroll
            for (int i = 1; i < NSPL; i++) lm = (cc[i] > lm) ? cc[i] : lm;
            unsigned long long mm = lm;
#pragma unroll
            for (int off = 16; off > 0; off >>= 1) {
                unsigned long long o = __shfl_xor_sync(0xFFFFFFFFu, mm, off);
                if (o > mm) mm = o;
            }
            unsigned has = __ballot_sync(0xFFFFFFFFu, lm == mm);
            int src = __ffs(has) - 1;
            if (lane == src) {
#pragma unroll
                for (int i = 0; i < NSPL; i++)
                    if (cc[i] == mm) cc[i] = 0ull;
            }
            if (lane == round) {
                myS = unflipf((unsigned)(mm >> 32));
                myN = (int)(0xFFFFFFFFu - (unsigned)(mm & 0xFFFFFFFFu));
            }
        }

        int warm = has_warm ? __ldg(warm_p) : 0;
        float alpha;
        if (warm) {
            float smax = __shfl_sync(0xFFFFFFFFu, myS, 0);
            float e = expf(myS - smax);
            float den = e;
#pragma unroll
            for (int off = 16; off > 0; off >>= 1) den += __shfl_xor_sync(0xFFFFFFFFu, den, off);
            alpha = e / den;
        } else {
            float rs = 0.f;
#pragma unroll
            for (int i = 0; i < 8; i++) rs += s_rs[i];
            float x = lambda * (myS - tau);
            float gg = 1.f / (1.f + expf(-x));
            float r = gg * expf(myS);
            float nr = r / (rs + EPSF);
            float snr = nr;
#pragma unroll
            for (int off = 16; off > 0; off >>= 1) snr += __shfl_xor_sync(0xFFFFFFFFu, snr, off);
            alpha = nr / (snr + EPSF);
        }
        out[b * KMAX + lane] = alpha;
        if (out_size >= 2 * B_ * KMAX)
            out[B_ * KMAX + b * KMAX + lane] = (float)myN;
    }
}

// ---------------- host launch ----------------
extern "C" void kernel_launch(void* const* d_in, const int* in_sizes, int n_in,
                              void* d_out, int out_size) {
    const float* z    = (const float*)d_in[0];   // [64,2048]
    const float* keys = (const float*)d_in[1];   // [8,100000,64]
    const float* wq   = (const float*)d_in[2];   // [8,64,2048]
    const float* aw   = (const float*)d_in[3];   // [8]
    const float* tau  = (const float*)d_in[4];   // scalar
    const float* lam  = (const float*)d_in[5];   // scalar
    const int* warm   = (n_in > 6) ? (const int*)d_in[6] : nullptr;

    k_proj_partial<<<dim3(16, 8), 256>>>(z, wq);
    k_qfinish<<<B_, 256>>>(aw);

    cudaFuncSetAttribute(k_mma, cudaFuncAttributeMaxDynamicSharedMemorySize, SM_TOTAL);
    k_mma<<<NT, 256, SM_TOTAL>>>(keys, tau, lam);

    k_tail<<<dim3(NSPL, B_), 256>>>(keys, tau, lam, warm, warm != nullptr,
                                    (float*)d_out, out_size);
}

// round 11
// speedup vs baseline: 1.2985x; 1.2985x over previous
#include <cuda_runtime.h>
#include <cuda_bf16.h>
#include <math.h>
#include <stdint.h>

// Problem constants (fixed by setup_inputs)
#define B_   64
#define S_   8
#define DK_  64
#define DA_  2048
#define N_   100000
#define KTOT 512        // S_*DK_
#define KMAX 32
#define NT   782        // n-tiles of 128
#define CAP  1024       // candidate buffer per b (smem)
#define DELTA 4e-3f     // threshold safety margin (>> bf16 score noise)
#define EPSF 1e-8f

// smem layout for k_mma (bytes)
#define STG_STRIDE 288            // 256B fp32 row + split-pad (conflict-free)
#define STG_BUF (128 * STG_STRIDE)   // 36864
#define SM_STG 0                     // 2 bufs: 73728
#define KSROW 144                    // bf16 row: 128B + 16 pad
#define KSBUF (128 * KSROW)          // 18432
#define SM_KS  (2 * STG_BUF)         // 73728; 2 bufs: 36864
#define SM_TOTAL (SM_KS + 2 * KSBUF) // 110592 (108 KB) -> 2 CTAs/SM

// ---------------- device scratch ----------------
__device__ float g_qpart[16 * B_ * KTOT];
__device__ float g_qhat[B_ * KTOT];               // fp32 q̂ (exact rescore)
__device__ uint4 g_qfrag[128 * 32];               // mma A fragments (64 KB)
__device__ float g_s[(size_t)B_ * N_];            // approx scores [b][n]
__device__ float g_rsp[B_ * NT];                  // rsum partials per (b,tile)
__device__ float g_bmax[B_ * NT];                 // per-(b,tile) max

// ================= helpers =================
__device__ __forceinline__ uint32_t smem_u32(const void* p) {
    uint32_t a;
    asm("{ .reg .u64 t; cvta.to.shared.u64 t, %1; cvt.u32.u64 %0, t; }" : "=r"(a) : "l"(p));
    return a;
}
__device__ __forceinline__ void cp_async16(uint32_t dst, const void* src) {
    asm volatile("cp.async.cg.shared.global [%0], [%1], 16;" :: "r"(dst), "l"(src));
}
#define CP_COMMIT() asm volatile("cp.async.commit_group;" ::: "memory")
#define CP_WAIT1()  asm volatile("cp.async.wait_group 1;" ::: "memory")
__device__ __forceinline__ void ldsm_x4(uint32_t& r0, uint32_t& r1, uint32_t& r2,
                                        uint32_t& r3, uint32_t addr) {
    asm volatile("ldmatrix.sync.aligned.m8n8.x4.shared.b16 {%0,%1,%2,%3}, [%4];"
                 : "=r"(r0), "=r"(r1), "=r"(r2), "=r"(r3) : "r"(addr));
}
__device__ __forceinline__ void mma16816(float* c, const uint32_t* a,
                                         uint32_t b0, uint32_t b1) {
    asm volatile(
        "mma.sync.aligned.m16n8k16.row.col.f32.bf16.bf16.f32 "
        "{%0,%1,%2,%3}, {%4,%5,%6,%7}, {%8,%9}, {%0,%1,%2,%3};"
        : "+f"(c[0]), "+f"(c[1]), "+f"(c[2]), "+f"(c[3])
        : "r"(a[0]), "r"(a[1]), "r"(a[2]), "r"(a[3]), "r"(b0), "r"(b1));
}
__device__ __forceinline__ unsigned flipf(float f) {
    unsigned u = __float_as_uint(f);
    return (u & 0x80000000u) ? ~u : (u | 0x80000000u);
}
__device__ __forceinline__ float unflipf(unsigned u) {
    return __uint_as_float((u & 0x80000000u) ? (u & 0x7FFFFFFFu) : ~u);
}
// 0-MUFU sigmoid(lambda(s-tau)) * exp(s) approximation (rsum only; ~0.1% acc)
__device__ __forceinline__ float rsum_term(float s, float lambda, float tau) {
    float e = 1.f + s * (1.f + s * (0.5f + s * (0.16666667f + s * (0.041666667f + s * 0.0083333333f))));
    float x = lambda * (s - tau);
    float ax = fabsf(x);
    float t;
    if (ax >= 4.5f) {
        t = 1.f;
    } else {
        float y = 0.5f * ax, y2 = y * y;
        float num = y * (27.f + y2);
        float den = fmaf(9.f, y2, 27.f);
        float rc = fmaf(den, -5.10e-4f, 0.05081f);
        rc = rc * (2.f - den * rc);
        rc = rc * (2.f - den * rc);
        t = fminf(num * rc, 1.f);
    }
    float g = fmaf(copysignf(t, x), 0.5f, 0.5f);
    return g * e;
}

// ---------------- K1a: query projection partial GEMM ----------------
__global__ void __launch_bounds__(256) k_proj_partial(const float* __restrict__ z,
                                                      const float* __restrict__ wq) {
    __shared__ float zt[64][33];
    __shared__ float wt[64][33];
    int tid = threadIdx.x;
    int tx = tid & 15, ty = tid >> 4;
    int a_base = blockIdx.x * 128;
    int sk_base = blockIdx.y * 64;
    float acc[4][4] = {};
    for (int t = 0; t < 4; t++) {
        int a0 = a_base + t * 32;
        for (int idx = tid; idx < 64 * 32; idx += 256) {
            int r = idx >> 5, c = idx & 31;
            zt[r][c] = z[r * DA_ + a0 + c];
            wt[r][c] = wq[(size_t)(sk_base + r) * DA_ + a0 + c];
        }
        __syncthreads();
#pragma unroll
        for (int a = 0; a < 32; a++) {
            float zv[4], wv[4];
#pragma unroll
            for (int i = 0; i < 4; i++) zv[i] = zt[4 * ty + i][a];
#pragma unroll
            for (int j = 0; j < 4; j++) wv[j] = wt[4 * tx + j][a];
#pragma unroll
            for (int i = 0; i < 4; i++)
#pragma unroll
                for (int j = 0; j < 4; j++) acc[i][j] += zv[i] * wv[j];
        }
        __syncthreads();
    }
#pragma unroll
    for (int i = 0; i < 4; i++)
#pragma unroll
        for (int j = 0; j < 4; j++)
            g_qpart[blockIdx.x * (B_ * KTOT) + (4 * ty + i) * KTOT + sk_base + 4 * tx + j] = acc[i][j];
}

// ---------------- K1b: reduce + normalize + softmax + emit fragments -------
__global__ void __launch_bounds__(256) k_qfinish(const float* __restrict__ aw) {
    __shared__ __nv_bfloat16 shq[8][64];
    int b = blockIdx.x;
    int tid = threadIdx.x;
    int s = tid >> 5, lane = tid & 31;
    int idx0 = b * KTOT + s * 64 + lane;
    int idx1 = idx0 + 32;

    float q0 = 0.f, q1 = 0.f;
#pragma unroll
    for (int p = 0; p < 16; p++) {
        q0 += g_qpart[p * (B_ * KTOT) + idx0];
        q1 += g_qpart[p * (B_ * KTOT) + idx1];
    }
    float ss = q0 * q0 + q1 * q1;
#pragma unroll
    for (int off = 16; off > 0; off >>= 1) ss += __shfl_xor_sync(0xFFFFFFFFu, ss, off);
    float m = aw[0];
#pragma unroll
    for (int i = 1; i < 8; i++) m = fmaxf(m, aw[i]);
    float den = 0.f, es = 0.f;
#pragma unroll
    for (int i = 0; i < 8; i++) {
        float e = expf(aw[i] - m);
        den += e;
        if (i == s) es = e;
    }
    float scale = (es / den) / (sqrtf(ss) + EPSF);
    float h0 = q0 * scale, h1 = q1 * scale;
    g_qhat[idx0] = h0;
    g_qhat[idx1] = h1;
    shq[s][lane] = __float2bfloat16(h0);
    shq[s][lane + 32] = __float2bfloat16(h1);
    __syncwarp();

    int kc = lane >> 3, t = (lane >> 1) & 3, h = lane & 1;
    int col = kc * 16 + h * 8 + 2 * t;
    __nv_bfloat162 pr = __halves2bfloat162(*(__nv_bfloat16*)&shq[s][col],
                                           *(__nv_bfloat16*)&shq[s][col + 1]);
    uint32_t val = *reinterpret_cast<uint32_t*>(&pr);
    int gp = b & 15;
    int frag = (s * 4 + kc) * 4 + (b >> 4);
    int comp = 2 * h + (gp >= 8 ? 1 : 0);
    int lanep = (gp & 7) * 4 + t;
    reinterpret_cast<uint32_t*>(g_qfrag)[frag * 128 + lanep * 4 + comp] = val;
}

// ---------------- K2: bf16 HMMA score GEMM, cp.async depth-2 pipeline ------
__global__ void __launch_bounds__(256, 2) k_mma(const float* __restrict__ keys,
                                                const float* __restrict__ tau_p,
                                                const float* __restrict__ lam_p) {
    extern __shared__ char smem[];
    __shared__ float s_rs[2][64];
    __shared__ float s_bm[2][64];
    uint32_t sb = smem_u32(smem);
    int tid = threadIdx.x;
    int wid = tid >> 5, lane = tid & 31;
    int wb = wid & 3, wn = wid >> 2;
    int n0 = blockIdx.x * 128;

    int r = tid >> 1, hf = tid & 1;
    int nrow = n0 + r;
    if (nrow >= N_) nrow = N_ - 1;
    const float* krow0 = keys + (size_t)nrow * DK_ + hf * 32;
    uint32_t mystg = sb + SM_STG + r * STG_STRIDE + hf * 144;

#pragma unroll
    for (int c = 0; c < 8; c++) cp_async16(mystg + c * 16, krow0 + c * 4);
    CP_COMMIT();
#pragma unroll
    for (int c = 0; c < 8; c++)
        cp_async16(mystg + STG_BUF + c * 16, krow0 + (size_t)N_ * DK_ + c * 4);
    CP_COMMIT();

    float acc[8][4] = {};
    int b_rowlane = wn * 64 + (lane & 7);
    int b_kof = (lane >> 3) * 8;

    for (int s = 0; s < S_; s++) {
        uint32_t stg = (s & 1) * STG_BUF;
        CP_WAIT1();
        __syncthreads();

        float4 v[8];
        const float4* sp = reinterpret_cast<const float4*>(smem + stg + r * STG_STRIDE + hf * 144);
#pragma unroll
        for (int j = 0; j < 8; j++) v[j] = sp[j];
        float ssv = 0.f;
#pragma unroll
        for (int j = 0; j < 8; j++)
            ssv += v[j].x * v[j].x + v[j].y * v[j].y + v[j].z * v[j].z + v[j].w * v[j].w;
        ssv += __shfl_xor_sync(0xFFFFFFFFu, ssv, 1);
        float inv = rsqrtf(ssv);

        char* rowp = smem + SM_KS + (s & 1) * KSBUF + r * KSROW + hf * 64;
#pragma unroll
        for (int j = 0; j < 4; j++) {
            float4 a = v[2 * j], b4 = v[2 * j + 1];
            __nv_bfloat162 p0 = __float22bfloat162_rn(make_float2(a.x * inv, a.y * inv));
            __nv_bfloat162 p1 = __float22bfloat162_rn(make_float2(a.z * inv, a.w * inv));
            __nv_bfloat162 p2 = __float22bfloat162_rn(make_float2(b4.x * inv, b4.y * inv));
            __nv_bfloat162 p3 = __float22bfloat162_rn(make_float2(b4.z * inv, b4.w * inv));
            uint4 pk;
            pk.x = *reinterpret_cast<uint32_t*>(&p0);
            pk.y = *reinterpret_cast<uint32_t*>(&p1);
            pk.z = *reinterpret_cast<uint32_t*>(&p2);
            pk.w = *reinterpret_cast<uint32_t*>(&p3);
            *reinterpret_cast<uint4*>(rowp + j * 16) = pk;
        }
        __syncthreads();

        if (s + 2 < S_) {
            const float* src = krow0 + (size_t)(s + 2) * N_ * DK_;
#pragma unroll
            for (int c = 0; c < 8; c++) cp_async16(mystg + stg + c * 16, src + c * 4);
        }
        CP_COMMIT();

        uint32_t afr[4][4];
#pragma unroll
        for (int kc = 0; kc < 4; kc++) {
            uint4 qf = __ldg(&g_qfrag[((s * 4 + kc) * 4 + wb) * 32 + lane]);
            afr[kc][0] = qf.x; afr[kc][1] = qf.y; afr[kc][2] = qf.z; afr[kc][3] = qf.w;
        }
        uint32_t bufo = SM_KS + (s & 1) * KSBUF;
#pragma unroll
        for (int ng = 0; ng < 8; ng++) {
            uint32_t baddr = sb + bufo + (b_rowlane + ng * 8) * KSROW + b_kof * 2;
            uint32_t bb[8];
            ldsm_x4(bb[0], bb[1], bb[2], bb[3], baddr);
            ldsm_x4(bb[4], bb[5], bb[6], bb[7], baddr + 64);
#pragma unroll
            for (int kc = 0; kc < 4; kc++)
                mma16816(acc[ng], afr[kc], bb[kc * 2], bb[kc * 2 + 1]);
        }
    }

    float lambda = __ldg(lam_p), tau = __ldg(tau_p);
    int brow = wb * 16 + (lane >> 2);
    int ncol0 = n0 + wn * 64 + 2 * (lane & 3);
    float rs0 = 0.f, rs1 = 0.f, bm0 = -1e30f, bm1 = -1e30f;
#pragma unroll
    for (int ng = 0; ng < 8; ng++) {
        int n = ncol0 + ng * 8;
        if (n < N_) {
            *reinterpret_cast<float2*>(&g_s[(size_t)brow * N_ + n]) =
                make_float2(acc[ng][0], acc[ng][1]);
            *reinterpret_cast<float2*>(&g_s[(size_t)(brow + 8) * N_ + n]) =
                make_float2(acc[ng][2], acc[ng][3]);
            rs0 += rsum_term(acc[ng][0], lambda, tau) + rsum_term(acc[ng][1], lambda, tau);
            rs1 += rsum_term(acc[ng][2], lambda, tau) + rsum_term(acc[ng][3], lambda, tau);
            bm0 = fmaxf(bm0, fmaxf(acc[ng][0], acc[ng][1]));
            bm1 = fmaxf(bm1, fmaxf(acc[ng][2], acc[ng][3]));
        }
    }
#pragma unroll
    for (int off = 1; off <= 2; off <<= 1) {
        rs0 += __shfl_xor_sync(0xFFFFFFFFu, rs0, off);
        rs1 += __shfl_xor_sync(0xFFFFFFFFu, rs1, off);
        bm0 = fmaxf(bm0, __shfl_xor_sync(0xFFFFFFFFu, bm0, off));
        bm1 = fmaxf(bm1, __shfl_xor_sync(0xFFFFFFFFu, bm1, off));
    }
    if ((lane & 3) == 0) {
        s_rs[wn][brow] = rs0; s_rs[wn][brow + 8] = rs1;
        s_bm[wn][brow] = bm0; s_bm[wn][brow + 8] = bm1;
    }
    __syncthreads();
    if (tid < 64) {
        g_rsp[tid * NT + blockIdx.x] = s_rs[0][tid] + s_rs[1][tid];
        g_bmax[tid * NT + blockIdx.x] = fmaxf(s_bm[0][tid], s_bm[1][tid]);
    }
}

// ---------------- K3: fused tail, short-chain version -----------------------
// One block per b. Register bisection (warp 0, no barriers), aspect-parallel
// rescore (8 threads/candidate), rank-based top-32 selection.
__global__ void __launch_bounds__(256) k_tail(const float* __restrict__ keys,
                                              const float* __restrict__ tau_p,
                                              const float* __restrict__ lam_p,
                                              const int* __restrict__ warm_p,
                                              int has_warm,
                                              float* __restrict__ out,
                                              int out_size) {
    __shared__ unsigned long long cand[CAP];       // 8 KB
    __shared__ unsigned long long top32[KMAX];
    __shared__ float sbm[NT];                      // tile maxima (3.1 KB)
    __shared__ int s_tiles[320];
    __shared__ float s_rs[8];
    __shared__ float s_T;
    __shared__ int s_ntile, s_ncand;
    int b = blockIdx.x;
    int tid = threadIdx.x;
    int wid = tid >> 5, lane = tid & 31;

    // Phase A: stage tile maxima to smem + rsum partial reduction
    float rsum = 0.f;
    for (int i = tid; i < NT; i += 256) {
        sbm[i] = g_bmax[b * NT + i];
        rsum += g_rsp[b * NT + i];
    }
#pragma unroll
    for (int off = 16; off > 0; off >>= 1) rsum += __shfl_xor_sync(0xFFFFFFFFu, rsum, off);
    if (lane == 0) s_rs[wid] = rsum;
    if (tid == 0) { s_ntile = 0; s_ncand = 0; }
    __syncthreads();

    // Phase B: warp 0 register bisection (no block barriers inside)
    if (wid == 0) {
        float mv[25];
#pragma unroll
        for (int j = 0; j < 25; j++) {
            int idx = lane * 25 + j;
            mv[j] = (idx < NT) ? sbm[idx] : -2.f;
        }
        float lo = -1.001f, hi = 1.001f;
        for (int it = 0; it < 16; it++) {
            float mid = 0.5f * (lo + hi);
            int c = 0;
#pragma unroll
            for (int j = 0; j < 25; j++) c += (mv[j] >= mid);
#pragma unroll
            for (int off = 16; off > 0; off >>= 1) c += __shfl_xor_sync(0xFFFFFFFFu, c, off);
            if (c >= KMAX) lo = mid; else hi = mid;
        }
        if (lane == 0) s_T = lo - DELTA;
    }
    __syncthreads();
    float T = s_T;

    // Phase C: qualifying tile list
    for (int i = tid; i < NT; i += 256)
        if (sbm[i] >= T) {
            int k = atomicAdd(&s_ntile, 1);
            if (k < 320) s_tiles[k] = i;
        }
    __syncthreads();
    int ntile = min(s_ntile, 320);

    // Phase D: collect candidates >= T (float4 loads)
    const float* srow = g_s + (size_t)b * N_;
    int total = ntile * 128;
    for (int base = tid * 4; base < total; base += 1024) {
        int tile = s_tiles[base >> 7];
        int n = tile * 128 + (base & 127);
        if (n + 3 < N_) {
            float4 v = *reinterpret_cast<const float4*>(srow + n);
            float sv[4] = {v.x, v.y, v.z, v.w};
#pragma unroll
            for (int j = 0; j < 4; j++) {
                if (sv[j] >= T) {
                    int idx = atomicAdd(&s_ncand, 1);
                    if (idx < CAP)
                        cand[idx] = ((unsigned long long)flipf(sv[j]) << 32) |
                                    (unsigned long long)(0xFFFFFFFFu - (unsigned)(n + j));
                }
            }
        } else {
#pragma unroll
            for (int j = 0; j < 4; j++) {
                int nn = n + j;
                if (nn < N_) {
                    float sv = srow[nn];
                    if (sv >= T) {
                        int idx = atomicAdd(&s_ncand, 1);
                        if (idx < CAP)
                            cand[idx] = ((unsigned long long)flipf(sv) << 32) |
                                        (unsigned long long)(0xFFFFFFFFu - (unsigned)nn);
                    }
                }
            }
        }
    }
    __syncthreads();
    int cnt = min(s_ncand, CAP);

    // Phase E: exact rescore, 8 threads per candidate (one aspect each)
    for (int base = 0; base < cnt; base += 32) {
        int ci = base + (tid >> 3);
        int s = tid & 7;
        bool act = (ci < cnt);
        float contrib = 0.f;
        unsigned n = 0;
        if (act) {
            n = 0xFFFFFFFFu - (unsigned)(cand[ci] & 0xFFFFFFFFu);
            const float4* kp = reinterpret_cast<const float4*>(keys + ((size_t)s * N_ + n) * DK_);
            const float4* qp = reinterpret_cast<const float4*>(g_qhat + b * KTOT + s * 64);
            float ss = 0.f, dt = 0.f;
#pragma unroll
            for (int j = 0; j < 16; j++) {
                float4 kv = __ldg(kp + j);
                float4 qv = qp[j];
                ss += kv.x * kv.x + kv.y * kv.y + kv.z * kv.z + kv.w * kv.w;
                dt += kv.x * qv.x + kv.y * qv.y + kv.z * qv.z + kv.w * qv.w;
            }
            contrib = dt / (sqrtf(ss) + EPSF);
        }
        // deterministic 8-lane butterfly sum (groups are lane-aligned)
        contrib += __shfl_xor_sync(0xFFFFFFFFu, contrib, 1);
        contrib += __shfl_xor_sync(0xFFFFFFFFu, contrib, 2);
        contrib += __shfl_xor_sync(0xFFFFFFFFu, contrib, 4);
        if (act && (tid & 7) == 0)
            cand[ci] = ((unsigned long long)flipf(contrib) << 32) |
                       (unsigned long long)(0xFFFFFFFFu - n);
    }
    __syncthreads();

    // Phase F: rank-based top-32 selection (keys unique -> exact ranks)
    for (int ci = tid; ci < cnt; ci += 256) {
        unsigned long long k = cand[ci];
        int r = 0;
        for (int j = 0; j < cnt; j++) r += (cand[j] > k);
        if (r < KMAX) top32[r] = k;
    }
    __syncthreads();

    // Phase G: alpha + output (warp 0)
    if (wid == 0) {
        float lambda = __ldg(lam_p), tau = __ldg(tau_p);
        unsigned long long key = top32[lane];
        float myS = unflipf((unsigned)(key >> 32));
        int myN = (int)(0xFFFFFFFFu - (unsigned)(key & 0xFFFFFFFFu));

        int warm = has_warm ? __ldg(warm_p) : 0;
        float alpha;
        if (warm) {
            float smax = __shfl_sync(0xFFFFFFFFu, myS, 0);
            float e = expf(myS - smax);
            float den = e;
#pragma unroll
            for (int off = 16; off > 0; off >>= 1) den += __shfl_xor_sync(0xFFFFFFFFu, den, off);
            alpha = e / den;
        } else {
            float rs = 0.f;
#pragma unroll
            for (int i = 0; i < 8; i++) rs += s_rs[i];
            float x = lambda * (myS - tau);
            float gg = 1.f / (1.f + expf(-x));
            float r = gg * expf(myS);
            float nr = r / (rs + EPSF);
            float snr = nr;
#pragma unroll
            for (int off = 16; off > 0; off >>= 1) snr += __shfl_xor_sync(0xFFFFFFFFu, snr, off);
            alpha = nr / (snr + EPSF);
        }
        out[b * KMAX + lane] = alpha;
        if (out_size >= 2 * B_ * KMAX)
            out[B_ * KMAX + b * KMAX + lane] = (float)myN;
    }
}

// ---------------- host launch ----------------
extern "C" void kernel_launch(void* const* d_in, const int* in_sizes, int n_in,
                              void* d_out, int out_size) {
    const float* z    = (const float*)d_in[0];   // [64,2048]
    const float* keys = (const float*)d_in[1];   // [8,100000,64]
    const float* wq   = (const float*)d_in[2];   // [8,64,2048]
    const float* aw   = (const float*)d_in[3];   // [8]
    const float* tau  = (const float*)d_in[4];   // scalar
    const float* lam  = (const float*)d_in[5];   // scalar
    const int* warm   = (n_in > 6) ? (const int*)d_in[6] : nullptr;

    k_proj_partial<<<dim3(16, 8), 256>>>(z, wq);
    k_qfinish<<<B_, 256>>>(aw);

    cudaFuncSetAttribute(k_mma, cudaFuncAttributeMaxDynamicSharedMemorySize, SM_TOTAL);
    k_mma<<<NT, 256, SM_TOTAL>>>(keys, tau, lam);

    k_tail<<<B_, 256>>>(keys, tau, lam, warm, warm != nullptr, (float*)d_out, out_size);
}

// round 12
// speedup vs baseline: 1.3431x; 1.0343x over previous
#include <cuda_runtime.h>
#include <cuda_bf16.h>
#include <math.h>
#include <stdint.h>

// Problem constants (fixed by setup_inputs)
#define B_   64
#define S_   8
#define DK_  64
#define DA_  2048
#define N_   100000
#define KTOT 512        // S_*DK_
#define KMAX 32
#define NT   782        // n-tiles of 128
#define CAP  1024       // candidate buffer per b (smem)
#define NTH  512        // k_tail threads
#define DELTA 4e-3f     // threshold safety margin (>> bf16 score+storage noise)
#define EPSF 1e-8f

// smem layout for k_mma (bytes)
#define STG_STRIDE 288            // 256B fp32 row + split-pad (conflict-free)
#define STG_BUF (128 * STG_STRIDE)   // 36864
#define SM_STG 0                     // 2 bufs: 73728
#define KSROW 144                    // bf16 row: 128B + 16 pad
#define KSBUF (128 * KSROW)          // 18432
#define SM_KS  (2 * STG_BUF)         // 73728; 2 bufs: 36864
#define SM_TOTAL (SM_KS + 2 * KSBUF) // 110592 (108 KB) -> 2 CTAs/SM

// ---------------- device scratch ----------------
__device__ float g_qpart[16 * B_ * KTOT];
__device__ float g_qhat[B_ * KTOT];               // fp32 q̂ (exact rescore)
__device__ uint4 g_qfrag[128 * 32];               // mma A fragments (64 KB)
__device__ __nv_bfloat16 g_sb[(size_t)B_ * N_];   // approx scores bf16 (12.8 MB)
__device__ float g_rsp[B_ * NT];                  // rsum partials per (b,tile)
__device__ float g_bmax[B_ * NT];                 // per-(b,tile) max (fp32)

// ================= helpers =================
__device__ __forceinline__ uint32_t smem_u32(const void* p) {
    uint32_t a;
    asm("{ .reg .u64 t; cvta.to.shared.u64 t, %1; cvt.u32.u64 %0, t; }" : "=r"(a) : "l"(p));
    return a;
}
__device__ __forceinline__ void cp_async16(uint32_t dst, const void* src) {
    asm volatile("cp.async.cg.shared.global [%0], [%1], 16;" :: "r"(dst), "l"(src));
}
#define CP_COMMIT() asm volatile("cp.async.commit_group;" ::: "memory")
#define CP_WAIT1()  asm volatile("cp.async.wait_group 1;" ::: "memory")
__device__ __forceinline__ void ldsm_x4(uint32_t& r0, uint32_t& r1, uint32_t& r2,
                                        uint32_t& r3, uint32_t addr) {
    asm volatile("ldmatrix.sync.aligned.m8n8.x4.shared.b16 {%0,%1,%2,%3}, [%4];"
                 : "=r"(r0), "=r"(r1), "=r"(r2), "=r"(r3) : "r"(addr));
}
__device__ __forceinline__ void mma16816(float* c, const uint32_t* a,
                                         uint32_t b0, uint32_t b1) {
    asm volatile(
        "mma.sync.aligned.m16n8k16.row.col.f32.bf16.bf16.f32 "
        "{%0,%1,%2,%3}, {%4,%5,%6,%7}, {%8,%9}, {%0,%1,%2,%3};"
        : "+f"(c[0]), "+f"(c[1]), "+f"(c[2]), "+f"(c[3])
        : "r"(a[0]), "r"(a[1]), "r"(a[2]), "r"(a[3]), "r"(b0), "r"(b1));
}
__device__ __forceinline__ unsigned flipf(float f) {
    unsigned u = __float_as_uint(f);
    return (u & 0x80000000u) ? ~u : (u | 0x80000000u);
}
__device__ __forceinline__ float unflipf(unsigned u) {
    return __uint_as_float((u & 0x80000000u) ? (u & 0x7FFFFFFFu) : ~u);
}
// 0-MUFU sigmoid(lambda(s-tau)) * exp(s) approximation (rsum only; ~0.1% acc)
__device__ __forceinline__ float rsum_term(float s, float lambda, float tau) {
    float e = 1.f + s * (1.f + s * (0.5f + s * (0.16666667f + s * (0.041666667f + s * 0.0083333333f))));
    float x = lambda * (s - tau);
    float ax = fabsf(x);
    float t;
    if (ax >= 4.5f) {
        t = 1.f;
    } else {
        float y = 0.5f * ax, y2 = y * y;
        float num = y * (27.f + y2);
        float den = fmaf(9.f, y2, 27.f);
        float rc = fmaf(den, -5.10e-4f, 0.05081f);
        rc = rc * (2.f - den * rc);
        rc = rc * (2.f - den * rc);
        t = fminf(num * rc, 1.f);
    }
    float g = fmaf(copysignf(t, x), 0.5f, 0.5f);
    return g * e;
}

// ---------------- K1a: query projection partial GEMM ----------------
__global__ void __launch_bounds__(256) k_proj_partial(const float* __restrict__ z,
                                                      const float* __restrict__ wq) {
    __shared__ float zt[64][33];
    __shared__ float wt[64][33];
    int tid = threadIdx.x;
    int tx = tid & 15, ty = tid >> 4;
    int a_base = blockIdx.x * 128;
    int sk_base = blockIdx.y * 64;
    float acc[4][4] = {};
    for (int t = 0; t < 4; t++) {
        int a0 = a_base + t * 32;
        for (int idx = tid; idx < 64 * 32; idx += 256) {
            int r = idx >> 5, c = idx & 31;
            zt[r][c] = z[r * DA_ + a0 + c];
            wt[r][c] = wq[(size_t)(sk_base + r) * DA_ + a0 + c];
        }
        __syncthreads();
#pragma unroll
        for (int a = 0; a < 32; a++) {
            float zv[4], wv[4];
#pragma unroll
            for (int i = 0; i < 4; i++) zv[i] = zt[4 * ty + i][a];
#pragma unroll
            for (int j = 0; j < 4; j++) wv[j] = wt[4 * tx + j][a];
#pragma unroll
            for (int i = 0; i < 4; i++)
#pragma unroll
                for (int j = 0; j < 4; j++) acc[i][j] += zv[i] * wv[j];
        }
        __syncthreads();
    }
#pragma unroll
    for (int i = 0; i < 4; i++)
#pragma unroll
        for (int j = 0; j < 4; j++)
            g_qpart[blockIdx.x * (B_ * KTOT) + (4 * ty + i) * KTOT + sk_base + 4 * tx + j] = acc[i][j];
}

// ---------------- K1b: reduce + normalize + softmax + emit fragments -------
__global__ void __launch_bounds__(256) k_qfinish(const float* __restrict__ aw) {
    __shared__ __nv_bfloat16 shq[8][64];
    int b = blockIdx.x;
    int tid = threadIdx.x;
    int s = tid >> 5, lane = tid & 31;
    int idx0 = b * KTOT + s * 64 + lane;
    int idx1 = idx0 + 32;

    float q0 = 0.f, q1 = 0.f;
#pragma unroll
    for (int p = 0; p < 16; p++) {
        q0 += g_qpart[p * (B_ * KTOT) + idx0];
        q1 += g_qpart[p * (B_ * KTOT) + idx1];
    }
    float ss = q0 * q0 + q1 * q1;
#pragma unroll
    for (int off = 16; off > 0; off >>= 1) ss += __shfl_xor_sync(0xFFFFFFFFu, ss, off);
    float m = aw[0];
#pragma unroll
    for (int i = 1; i < 8; i++) m = fmaxf(m, aw[i]);
    float den = 0.f, es = 0.f;
#pragma unroll
    for (int i = 0; i < 8; i++) {
        float e = expf(aw[i] - m);
        den += e;
        if (i == s) es = e;
    }
    float scale = (es / den) / (sqrtf(ss) + EPSF);
    float h0 = q0 * scale, h1 = q1 * scale;
    g_qhat[idx0] = h0;
    g_qhat[idx1] = h1;
    shq[s][lane] = __float2bfloat16(h0);
    shq[s][lane + 32] = __float2bfloat16(h1);
    __syncwarp();

    int kc = lane >> 3, t = (lane >> 1) & 3, h = lane & 1;
    int col = kc * 16 + h * 8 + 2 * t;
    __nv_bfloat162 pr = __halves2bfloat162(*(__nv_bfloat16*)&shq[s][col],
                                           *(__nv_bfloat16*)&shq[s][col + 1]);
    uint32_t val = *reinterpret_cast<uint32_t*>(&pr);
    int gp = b & 15;
    int frag = (s * 4 + kc) * 4 + (b >> 4);
    int comp = 2 * h + (gp >= 8 ? 1 : 0);
    int lanep = (gp & 7) * 4 + t;
    reinterpret_cast<uint32_t*>(g_qfrag)[frag * 128 + lanep * 4 + comp] = val;
}

// ---------------- K2: bf16 HMMA score GEMM, cp.async depth-2 pipeline ------
__global__ void __launch_bounds__(256, 2) k_mma(const float* __restrict__ keys,
                                                const float* __restrict__ tau_p,
                                                const float* __restrict__ lam_p) {
    extern __shared__ char smem[];
    __shared__ float s_rs[2][64];
    __shared__ float s_bm[2][64];
    uint32_t sb = smem_u32(smem);
    int tid = threadIdx.x;
    int wid = tid >> 5, lane = tid & 31;
    int wb = wid & 3, wn = wid >> 2;
    int n0 = blockIdx.x * 128;

    int r = tid >> 1, hf = tid & 1;
    int nrow = n0 + r;
    if (nrow >= N_) nrow = N_ - 1;
    const float* krow0 = keys + (size_t)nrow * DK_ + hf * 32;
    uint32_t mystg = sb + SM_STG + r * STG_STRIDE + hf * 144;

#pragma unroll
    for (int c = 0; c < 8; c++) cp_async16(mystg + c * 16, krow0 + c * 4);
    CP_COMMIT();
#pragma unroll
    for (int c = 0; c < 8; c++)
        cp_async16(mystg + STG_BUF + c * 16, krow0 + (size_t)N_ * DK_ + c * 4);
    CP_COMMIT();

    float acc[8][4] = {};
    int b_rowlane = wn * 64 + (lane & 7);
    int b_kof = (lane >> 3) * 8;

    for (int s = 0; s < S_; s++) {
        uint32_t stg = (s & 1) * STG_BUF;
        CP_WAIT1();
        __syncthreads();

        float4 v[8];
        const float4* sp = reinterpret_cast<const float4*>(smem + stg + r * STG_STRIDE + hf * 144);
#pragma unroll
        for (int j = 0; j < 8; j++) v[j] = sp[j];
        float ssv = 0.f;
#pragma unroll
        for (int j = 0; j < 8; j++)
            ssv += v[j].x * v[j].x + v[j].y * v[j].y + v[j].z * v[j].z + v[j].w * v[j].w;
        ssv += __shfl_xor_sync(0xFFFFFFFFu, ssv, 1);
        float inv = rsqrtf(ssv);

        char* rowp = smem + SM_KS + (s & 1) * KSBUF + r * KSROW + hf * 64;
#pragma unroll
        for (int j = 0; j < 4; j++) {
            float4 a = v[2 * j], b4 = v[2 * j + 1];
            __nv_bfloat162 p0 = __float22bfloat162_rn(make_float2(a.x * inv, a.y * inv));
            __nv_bfloat162 p1 = __float22bfloat162_rn(make_float2(a.z * inv, a.w * inv));
            __nv_bfloat162 p2 = __float22bfloat162_rn(make_float2(b4.x * inv, b4.y * inv));
            __nv_bfloat162 p3 = __float22bfloat162_rn(make_float2(b4.z * inv, b4.w * inv));
            uint4 pk;
            pk.x = *reinterpret_cast<uint32_t*>(&p0);
            pk.y = *reinterpret_cast<uint32_t*>(&p1);
            pk.z = *reinterpret_cast<uint32_t*>(&p2);
            pk.w = *reinterpret_cast<uint32_t*>(&p3);
            *reinterpret_cast<uint4*>(rowp + j * 16) = pk;
        }
        __syncthreads();

        if (s + 2 < S_) {
            const float* src = krow0 + (size_t)(s + 2) * N_ * DK_;
#pragma unroll
            for (int c = 0; c < 8; c++) cp_async16(mystg + stg + c * 16, src + c * 4);
        }
        CP_COMMIT();

        uint32_t afr[4][4];
#pragma unroll
        for (int kc = 0; kc < 4; kc++) {
            uint4 qf = __ldg(&g_qfrag[((s * 4 + kc) * 4 + wb) * 32 + lane]);
            afr[kc][0] = qf.x; afr[kc][1] = qf.y; afr[kc][2] = qf.z; afr[kc][3] = qf.w;
        }
        uint32_t bufo = SM_KS + (s & 1) * KSBUF;
#pragma unroll
        for (int ng = 0; ng < 8; ng++) {
            uint32_t baddr = sb + bufo + (b_rowlane + ng * 8) * KSROW + b_kof * 2;
            uint32_t bb[8];
            ldsm_x4(bb[0], bb[1], bb[2], bb[3], baddr);
            ldsm_x4(bb[4], bb[5], bb[6], bb[7], baddr + 64);
#pragma unroll
            for (int kc = 0; kc < 4; kc++)
                mma16816(acc[ng], afr[kc], bb[kc * 2], bb[kc * 2 + 1]);
        }
    }

    // epilogue: bf16 score store + fused rsum partial & tile max (fp32 accs)
    float lambda = __ldg(lam_p), tau = __ldg(tau_p);
    int brow = wb * 16 + (lane >> 2);
    int ncol0 = n0 + wn * 64 + 2 * (lane & 3);
    float rs0 = 0.f, rs1 = 0.f, bm0 = -1e30f, bm1 = -1e30f;
#pragma unroll
    for (int ng = 0; ng < 8; ng++) {
        int n = ncol0 + ng * 8;
        if (n < N_) {
            __nv_bfloat162 pa = __float22bfloat162_rn(make_float2(acc[ng][0], acc[ng][1]));
            __nv_bfloat162 pb = __float22bfloat162_rn(make_float2(acc[ng][2], acc[ng][3]));
            *reinterpret_cast<uint32_t*>(&g_sb[(size_t)brow * N_ + n]) =
                *reinterpret_cast<uint32_t*>(&pa);
            *reinterpret_cast<uint32_t*>(&g_sb[(size_t)(brow + 8) * N_ + n]) =
                *reinterpret_cast<uint32_t*>(&pb);
            rs0 += rsum_term(acc[ng][0], lambda, tau) + rsum_term(acc[ng][1], lambda, tau);
            rs1 += rsum_term(acc[ng][2], lambda, tau) + rsum_term(acc[ng][3], lambda, tau);
            bm0 = fmaxf(bm0, fmaxf(acc[ng][0], acc[ng][1]));
            bm1 = fmaxf(bm1, fmaxf(acc[ng][2], acc[ng][3]));
        }
    }
#pragma unroll
    for (int off = 1; off <= 2; off <<= 1) {
        rs0 += __shfl_xor_sync(0xFFFFFFFFu, rs0, off);
        rs1 += __shfl_xor_sync(0xFFFFFFFFu, rs1, off);
        bm0 = fmaxf(bm0, __shfl_xor_sync(0xFFFFFFFFu, bm0, off));
        bm1 = fmaxf(bm1, __shfl_xor_sync(0xFFFFFFFFu, bm1, off));
    }
    if ((lane & 3) == 0) {
        s_rs[wn][brow] = rs0; s_rs[wn][brow + 8] = rs1;
        s_bm[wn][brow] = bm0; s_bm[wn][brow + 8] = bm1;
    }
    __syncthreads();
    if (tid < 64) {
        g_rsp[tid * NT + blockIdx.x] = s_rs[0][tid] + s_rs[1][tid];
        g_bmax[tid * NT + blockIdx.x] = fmaxf(s_bm[0][tid], s_bm[1][tid]);
    }
}

// ---------------- K3: fused tail (512 threads, bf16 scores) ----------------
__global__ void __launch_bounds__(NTH) k_tail(const float* __restrict__ keys,
                                              const float* __restrict__ tau_p,
                                              const float* __restrict__ lam_p,
                                              const int* __restrict__ warm_p,
                                              int has_warm,
                                              float* __restrict__ out,
                                              int out_size) {
    __shared__ unsigned long long cand[CAP];       // 8 KB
    __shared__ unsigned long long top32[KMAX];
    __shared__ float sbm[NT];                      // tile maxima (3.1 KB)
    __shared__ int s_tiles[320];
    __shared__ float s_rs[16];
    __shared__ float s_T;
    __shared__ int s_ntile, s_ncand;
    int b = blockIdx.x;
    int tid = threadIdx.x;
    int wid = tid >> 5, lane = tid & 31;

    // Phase A: stage tile maxima to smem + rsum partial reduction
    float rsum = 0.f;
    for (int i = tid; i < NT; i += NTH) {
        sbm[i] = g_bmax[b * NT + i];
        rsum += g_rsp[b * NT + i];
    }
#pragma unroll
    for (int off = 16; off > 0; off >>= 1) rsum += __shfl_xor_sync(0xFFFFFFFFu, rsum, off);
    if (lane == 0) s_rs[wid] = rsum;
    if (tid == 0) { s_ntile = 0; s_ncand = 0; }
    __syncthreads();

    // Phase B: warp 0 register bisection (no block barriers inside)
    if (wid == 0) {
        float mv[25];
#pragma unroll
        for (int j = 0; j < 25; j++) {
            int idx = lane * 25 + j;
            mv[j] = (idx < NT) ? sbm[idx] : -2.f;
        }
        float lo = -1.001f, hi = 1.001f;
        for (int it = 0; it < 16; it++) {
            float mid = 0.5f * (lo + hi);
            int c = 0;
#pragma unroll
            for (int j = 0; j < 25; j++) c += (mv[j] >= mid);
#pragma unroll
            for (int off = 16; off > 0; off >>= 1) c += __shfl_xor_sync(0xFFFFFFFFu, c, off);
            if (c >= KMAX) lo = mid; else hi = mid;
        }
        if (lane == 0) s_T = lo - DELTA;
    }
    __syncthreads();
    float T = s_T;

    // Phase C: qualifying tile list
    for (int i = tid; i < NT; i += NTH)
        if (sbm[i] >= T) {
            int k = atomicAdd(&s_ntile, 1);
            if (k < 320) s_tiles[k] = i;
        }
    __syncthreads();
    int ntile = min(s_ntile, 320);

    // Phase D: collect candidates >= T from bf16 scores (uint4 = 8 scores)
    const __nv_bfloat16* srow = g_sb + (size_t)b * N_;
    int total = ntile * 128;
    for (int base = tid * 8; base < total; base += NTH * 8) {
        int tile = s_tiles[base >> 7];
        int n = tile * 128 + (base & 127);
        if (n + 7 < N_) {
            uint4 v = *reinterpret_cast<const uint4*>(srow + n);
            uint32_t w[4] = {v.x, v.y, v.z, v.w};
#pragma unroll
            for (int j = 0; j < 4; j++) {
                __nv_bfloat162 h = *reinterpret_cast<__nv_bfloat162*>(&w[j]);
                float f0 = __low2float(h), f1 = __high2float(h);
                if (f0 >= T) {
                    int idx = atomicAdd(&s_ncand, 1);
                    if (idx < CAP)
                        cand[idx] = ((unsigned long long)flipf(f0) << 32) |
                                    (unsigned long long)(0xFFFFFFFFu - (unsigned)(n + 2 * j));
                }
                if (f1 >= T) {
                    int idx = atomicAdd(&s_ncand, 1);
                    if (idx < CAP)
                        cand[idx] = ((unsigned long long)flipf(f1) << 32) |
                                    (unsigned long long)(0xFFFFFFFFu - (unsigned)(n + 2 * j + 1));
                }
            }
        } else {
#pragma unroll
            for (int j = 0; j < 8; j++) {
                int nn = n + j;
                if (nn < N_) {
                    float sv = __bfloat162float(srow[nn]);
                    if (sv >= T) {
                        int idx = atomicAdd(&s_ncand, 1);
                        if (idx < CAP)
                            cand[idx] = ((unsigned long long)flipf(sv) << 32) |
                                        (unsigned long long)(0xFFFFFFFFu - (unsigned)nn);
                    }
                }
            }
        }
    }
    __syncthreads();
    int cnt = min(s_ncand, CAP);

    // Phase E: exact rescore, 8 threads per candidate (one aspect each)
    for (int base = 0; base < cnt; base += NTH / 8) {
        int ci = base + (tid >> 3);
        int s = tid & 7;
        bool act = (ci < cnt);
        float contrib = 0.f;
        unsigned n = 0;
        if (act) {
            n = 0xFFFFFFFFu - (unsigned)(cand[ci] & 0xFFFFFFFFu);
            const float4* kp = reinterpret_cast<const float4*>(keys + ((size_t)s * N_ + n) * DK_);
            const float4* qp = reinterpret_cast<const float4*>(g_qhat + b * KTOT + s * 64);
            float ss = 0.f, dt = 0.f;
#pragma unroll
            for (int j = 0; j < 16; j++) {
                float4 kv = __ldg(kp + j);
                float4 qv = qp[j];
                ss += kv.x * kv.x + kv.y * kv.y + kv.z * kv.z + kv.w * kv.w;
                dt += kv.x * qv.x + kv.y * qv.y + kv.z * qv.z + kv.w * qv.w;
            }
            contrib = dt / (sqrtf(ss) + EPSF);
        }
        contrib += __shfl_xor_sync(0xFFFFFFFFu, contrib, 1);
        contrib += __shfl_xor_sync(0xFFFFFFFFu, contrib, 2);
        contrib += __shfl_xor_sync(0xFFFFFFFFu, contrib, 4);
        if (act && (tid & 7) == 0)
            cand[ci] = ((unsigned long long)flipf(contrib) << 32) |
                       (unsigned long long)(0xFFFFFFFFu - n);
    }
    __syncthreads();

    // Phase F: rank-based top-32 selection (keys unique -> exact ranks)
    for (int ci = tid; ci < cnt; ci += NTH) {
        unsigned long long k = cand[ci];
        int r = 0;
        for (int j = 0; j < cnt; j++) r += (cand[j] > k);
        if (r < KMAX) top32[r] = k;
    }
    __syncthreads();

    // Phase G: alpha + output (warp 0)
    if (wid == 0) {
        float lambda = __ldg(lam_p), tau = __ldg(tau_p);
        unsigned long long key = top32[lane];
        float myS = unflipf((unsigned)(key >> 32));
        int myN = (int)(0xFFFFFFFFu - (unsigned)(key & 0xFFFFFFFFu));

        int warm = has_warm ? __ldg(warm_p) : 0;
        float alpha;
        if (warm) {
            float smax = __shfl_sync(0xFFFFFFFFu, myS, 0);
            float e = expf(myS - smax);
            float den = e;
#pragma unroll
            for (int off = 16; off > 0; off >>= 1) den += __shfl_xor_sync(0xFFFFFFFFu, den, off);
            alpha = e / den;
        } else {
            float rs = 0.f;
#pragma unroll
            for (int i = 0; i < 16; i++) rs += s_rs[i];
            float x = lambda * (myS - tau);
            float gg = 1.f / (1.f + expf(-x));
            float r = gg * expf(myS);
            float nr = r / (rs + EPSF);
            float snr = nr;
#pragma unroll
            for (int off = 16; off > 0; off >>= 1) snr += __shfl_xor_sync(0xFFFFFFFFu, snr, off);
            alpha = nr / (snr + EPSF);
        }
        out[b * KMAX + lane] = alpha;
        if (out_size >= 2 * B_ * KMAX)
            out[B_ * KMAX + b * KMAX + lane] = (float)myN;
    }
}

// ---------------- host launch ----------------
extern "C" void kernel_launch(void* const* d_in, const int* in_sizes, int n_in,
                              void* d_out, int out_size) {
    const float* z    = (const float*)d_in[0];   // [64,2048]
    const float* keys = (const float*)d_in[1];   // [8,100000,64]
    const float* wq   = (const float*)d_in[2];   // [8,64,2048]
    const float* aw   = (const float*)d_in[3];   // [8]
    const float* tau  = (const float*)d_in[4];   // scalar
    const float* lam  = (const float*)d_in[5];   // scalar
    const int* warm   = (n_in > 6) ? (const int*)d_in[6] : nullptr;

    k_proj_partial<<<dim3(16, 8), 256>>>(z, wq);
    k_qfinish<<<B_, 256>>>(aw);

    cudaFuncSetAttribute(k_mma, cudaFuncAttributeMaxDynamicSharedMemorySize, SM_TOTAL);
    k_mma<<<NT, 256, SM_TOTAL>>>(keys, tau, lam);

    k_tail<<<B_, NTH>>>(keys, tau, lam, warm, warm != nullptr, (float*)d_out, out_size);
}

// round 13
// speedup vs baseline: 1.3908x; 1.0356x over previous
#include <cuda_runtime.h>
#include <cuda_bf16.h>
#include <math.h>
#include <stdint.h>

// Problem constants (fixed by setup_inputs)
#define B_   64
#define S_   8
#define DK_  64
#define DA_  2048
#define N_   100000
#define KTOT 512        // S_*DK_
#define KMAX 32
#define NT   782        // n-tiles of 128
#define CAP  1024       // candidate buffer per b (smem)
#define NTH  512        // k_tail threads
#define DELTA 4e-3f     // threshold safety margin (>> bf16 score+storage noise)
#define EPSF 1e-8f

// smem layout for k_mma (bytes)
#define STG_STRIDE 288            // 256B fp32 row + split-pad (conflict-free)
#define STG_BUF (128 * STG_STRIDE)   // 36864
#define SM_STG 0                     // 2 bufs: 73728
#define KSROW 144                    // bf16 row: 128B + 16 pad
#define KSBUF (128 * KSROW)          // 18432
#define SM_KS  (2 * STG_BUF)         // 73728; 2 bufs: 36864
#define SM_TOTAL (SM_KS + 2 * KSBUF) // 110592 (108 KB) -> 2 CTAs/SM

// ---------------- device scratch ----------------
__device__ float g_qpart[16 * B_ * KTOT];
__device__ float g_qhat[B_ * KTOT];               // fp32 q̂ (exact rescore)
__device__ uint4 g_qfrag[128 * 32];               // mma A fragments (64 KB)
__device__ __nv_bfloat16 g_sb[(size_t)B_ * N_];   // approx scores bf16 (12.8 MB)
__device__ float g_rsp[B_ * NT];                  // rsum partials per (b,tile)
__device__ float g_bmax[B_ * NT];                 // per-(b,tile) max (fp32)

// ================= helpers =================
__device__ __forceinline__ uint32_t smem_u32(const void* p) {
    uint32_t a;
    asm("{ .reg .u64 t; cvta.to.shared.u64 t, %1; cvt.u32.u64 %0, t; }" : "=r"(a) : "l"(p));
    return a;
}
__device__ __forceinline__ void cp_async16(uint32_t dst, const void* src) {
    asm volatile("cp.async.cg.shared.global [%0], [%1], 16;" :: "r"(dst), "l"(src));
}
#define CP_COMMIT() asm volatile("cp.async.commit_group;" ::: "memory")
#define CP_WAIT1()  asm volatile("cp.async.wait_group 1;" ::: "memory")
__device__ __forceinline__ void ldsm_x4(uint32_t& r0, uint32_t& r1, uint32_t& r2,
                                        uint32_t& r3, uint32_t addr) {
    asm volatile("ldmatrix.sync.aligned.m8n8.x4.shared.b16 {%0,%1,%2,%3}, [%4];"
                 : "=r"(r0), "=r"(r1), "=r"(r2), "=r"(r3) : "r"(addr));
}
__device__ __forceinline__ void mma16816(float* c, const uint32_t* a,
                                         uint32_t b0, uint32_t b1) {
    asm volatile(
        "mma.sync.aligned.m16n8k16.row.col.f32.bf16.bf16.f32 "
        "{%0,%1,%2,%3}, {%4,%5,%6,%7}, {%8,%9}, {%0,%1,%2,%3};"
        : "+f"(c[0]), "+f"(c[1]), "+f"(c[2]), "+f"(c[3])
        : "r"(a[0]), "r"(a[1]), "r"(a[2]), "r"(a[3]), "r"(b0), "r"(b1));
}
__device__ __forceinline__ unsigned flipf(float f) {
    unsigned u = __float_as_uint(f);
    return (u & 0x80000000u) ? ~u : (u | 0x80000000u);
}
__device__ __forceinline__ float unflipf(unsigned u) {
    return __uint_as_float((u & 0x80000000u) ? (u & 0x7FFFFFFFu) : ~u);
}
// 0-MUFU sigmoid(lambda(s-tau)) * exp(s) approximation (rsum only; ~0.1% acc)
__device__ __forceinline__ float rsum_term(float s, float lambda, float tau) {
    float e = 1.f + s * (1.f + s * (0.5f + s * (0.16666667f + s * (0.041666667f + s * 0.0083333333f))));
    float x = lambda * (s - tau);
    float ax = fabsf(x);
    float t;
    if (ax >= 4.5f) {
        t = 1.f;
    } else {
        float y = 0.5f * ax, y2 = y * y;
        float num = y * (27.f + y2);
        float den = fmaf(9.f, y2, 27.f);
        float rc = fmaf(den, -5.10e-4f, 0.05081f);
        rc = rc * (2.f - den * rc);
        rc = rc * (2.f - den * rc);
        t = fminf(num * rc, 1.f);
    }
    float g = fmaf(copysignf(t, x), 0.5f, 0.5f);
    return g * e;
}

// ---------------- K1a: query projection partial GEMM ----------------
__global__ void __launch_bounds__(256) k_proj_partial(const float* __restrict__ z,
                                                      const float* __restrict__ wq) {
    __shared__ float zt[64][33];
    __shared__ float wt[64][33];
    int tid = threadIdx.x;
    int tx = tid & 15, ty = tid >> 4;
    int a_base = blockIdx.x * 128;
    int sk_base = blockIdx.y * 64;
    float acc[4][4] = {};
    for (int t = 0; t < 4; t++) {
        int a0 = a_base + t * 32;
        for (int idx = tid; idx < 64 * 32; idx += 256) {
            int r = idx >> 5, c = idx & 31;
            zt[r][c] = z[r * DA_ + a0 + c];
            wt[r][c] = wq[(size_t)(sk_base + r) * DA_ + a0 + c];
        }
        __syncthreads();
#pragma unroll
        for (int a = 0; a < 32; a++) {
            float zv[4], wv[4];
#pragma unroll
            for (int i = 0; i < 4; i++) zv[i] = zt[4 * ty + i][a];
#pragma unroll
            for (int j = 0; j < 4; j++) wv[j] = wt[4 * tx + j][a];
#pragma unroll
            for (int i = 0; i < 4; i++)
#pragma unroll
                for (int j = 0; j < 4; j++) acc[i][j] += zv[i] * wv[j];
        }
        __syncthreads();
    }
#pragma unroll
    for (int i = 0; i < 4; i++)
#pragma unroll
        for (int j = 0; j < 4; j++)
            g_qpart[blockIdx.x * (B_ * KTOT) + (4 * ty + i) * KTOT + sk_base + 4 * tx + j] = acc[i][j];
}

// ---------------- K1b: reduce + normalize + softmax + emit fragments -------
__global__ void __launch_bounds__(256) k_qfinish(const float* __restrict__ aw) {
    __shared__ __nv_bfloat16 shq[8][64];
    int b = blockIdx.x;
    int tid = threadIdx.x;
    int s = tid >> 5, lane = tid & 31;
    int idx0 = b * KTOT + s * 64 + lane;
    int idx1 = idx0 + 32;

    float q0 = 0.f, q1 = 0.f;
#pragma unroll
    for (int p = 0; p < 16; p++) {
        q0 += g_qpart[p * (B_ * KTOT) + idx0];
        q1 += g_qpart[p * (B_ * KTOT) + idx1];
    }
    float ss = q0 * q0 + q1 * q1;
#pragma unroll
    for (int off = 16; off > 0; off >>= 1) ss += __shfl_xor_sync(0xFFFFFFFFu, ss, off);
    float m = aw[0];
#pragma unroll
    for (int i = 1; i < 8; i++) m = fmaxf(m, aw[i]);
    float den = 0.f, es = 0.f;
#pragma unroll
    for (int i = 0; i < 8; i++) {
        float e = expf(aw[i] - m);
        den += e;
        if (i == s) es = e;
    }
    float scale = (es / den) / (sqrtf(ss) + EPSF);
    float h0 = q0 * scale, h1 = q1 * scale;
    g_qhat[idx0] = h0;
    g_qhat[idx1] = h1;
    shq[s][lane] = __float2bfloat16(h0);
    shq[s][lane + 32] = __float2bfloat16(h1);
    __syncwarp();

    int kc = lane >> 3, t = (lane >> 1) & 3, h = lane & 1;
    int col = kc * 16 + h * 8 + 2 * t;
    __nv_bfloat162 pr = __halves2bfloat162(*(__nv_bfloat16*)&shq[s][col],
                                           *(__nv_bfloat16*)&shq[s][col + 1]);
    uint32_t val = *reinterpret_cast<uint32_t*>(&pr);
    int gp = b & 15;
    int frag = (s * 4 + kc) * 4 + (b >> 4);
    int comp = 2 * h + (gp >= 8 ? 1 : 0);
    int lanep = (gp & 7) * 4 + t;
    reinterpret_cast<uint32_t*>(g_qfrag)[frag * 128 + lanep * 4 + comp] = val;
}

// ---------------- K2: bf16 HMMA score GEMM, 32b x 32n warp tiles -----------
// 8 warps = 2 b-halves (wid&1 -> b-groups {0,1}/{2,3}) x 4 n-quarters (wid>>1).
// Each warp ldsm-loads only its own 32n B slice (no cross-warp duplication).
__global__ void __launch_bounds__(256, 2) k_mma(const float* __restrict__ keys,
                                                const float* __restrict__ tau_p,
                                                const float* __restrict__ lam_p) {
    extern __shared__ char smem[];
    __shared__ float s_rs[4][64];
    __shared__ float s_bm[4][64];
    uint32_t sb = smem_u32(smem);
    int tid = threadIdx.x;
    int wid = tid >> 5, lane = tid & 31;
    int wbh = wid & 1, wq = wid >> 1;
    int n0 = blockIdx.x * 128;

    int r = tid >> 1, hf = tid & 1;
    int nrow = n0 + r;
    if (nrow >= N_) nrow = N_ - 1;
    const float* krow0 = keys + (size_t)nrow * DK_ + hf * 32;
    uint32_t mystg = sb + SM_STG + r * STG_STRIDE + hf * 144;

#pragma unroll
    for (int c = 0; c < 8; c++) cp_async16(mystg + c * 16, krow0 + c * 4);
    CP_COMMIT();
#pragma unroll
    for (int c = 0; c < 8; c++)
        cp_async16(mystg + STG_BUF + c * 16, krow0 + (size_t)N_ * DK_ + c * 4);
    CP_COMMIT();

    float acc[2][4][4] = {};
    int b_rowlane = wq * 32 + (lane & 7);
    int b_kof = (lane >> 3) * 8;

    for (int s = 0; s < S_; s++) {
        uint32_t stg = (s & 1) * STG_BUF;
        CP_WAIT1();
        __syncthreads();

        float4 v[8];
        const float4* sp = reinterpret_cast<const float4*>(smem + stg + r * STG_STRIDE + hf * 144);
#pragma unroll
        for (int j = 0; j < 8; j++) v[j] = sp[j];
        float ssv = 0.f;
#pragma unroll
        for (int j = 0; j < 8; j++)
            ssv += v[j].x * v[j].x + v[j].y * v[j].y + v[j].z * v[j].z + v[j].w * v[j].w;
        ssv += __shfl_xor_sync(0xFFFFFFFFu, ssv, 1);
        float inv = rsqrtf(ssv);

        char* rowp = smem + SM_KS + (s & 1) * KSBUF + r * KSROW + hf * 64;
#pragma unroll
        for (int j = 0; j < 4; j++) {
            float4 a = v[2 * j], b4 = v[2 * j + 1];
            __nv_bfloat162 p0 = __float22bfloat162_rn(make_float2(a.x * inv, a.y * inv));
            __nv_bfloat162 p1 = __float22bfloat162_rn(make_float2(a.z * inv, a.w * inv));
            __nv_bfloat162 p2 = __float22bfloat162_rn(make_float2(b4.x * inv, b4.y * inv));
            __nv_bfloat162 p3 = __float22bfloat162_rn(make_float2(b4.z * inv, b4.w * inv));
            uint4 pk;
            pk.x = *reinterpret_cast<uint32_t*>(&p0);
            pk.y = *reinterpret_cast<uint32_t*>(&p1);
            pk.z = *reinterpret_cast<uint32_t*>(&p2);
            pk.w = *reinterpret_cast<uint32_t*>(&p3);
            *reinterpret_cast<uint4*>(rowp + j * 16) = pk;
        }
        __syncthreads();

        if (s + 2 < S_) {
            const float* src = krow0 + (size_t)(s + 2) * N_ * DK_;
#pragma unroll
            for (int c = 0; c < 8; c++) cp_async16(mystg + stg + c * 16, src + c * 4);
        }
        CP_COMMIT();

        // B fragments for this warp's 32n quarter (loaded once)
        uint32_t bufo = SM_KS + (s & 1) * KSBUF;
        uint32_t bbv[4][8];
#pragma unroll
        for (int ng = 0; ng < 4; ng++) {
            uint32_t baddr = sb + bufo + (b_rowlane + ng * 8) * KSROW + b_kof * 2;
            ldsm_x4(bbv[ng][0], bbv[ng][1], bbv[ng][2], bbv[ng][3], baddr);
            ldsm_x4(bbv[ng][4], bbv[ng][5], bbv[ng][6], bbv[ng][7], baddr + 64);
        }
        // two 16-row b-groups per warp
#pragma unroll
        for (int bg = 0; bg < 2; bg++) {
            int bgi = wbh * 2 + bg;
            uint32_t afr[4][4];
#pragma unroll
            for (int kc = 0; kc < 4; kc++) {
                uint4 qf = __ldg(&g_qfrag[((s * 4 + kc) * 4 + bgi) * 32 + lane]);
                afr[kc][0] = qf.x; afr[kc][1] = qf.y; afr[kc][2] = qf.z; afr[kc][3] = qf.w;
            }
#pragma unroll
            for (int ng = 0; ng < 4; ng++)
#pragma unroll
                for (int kc = 0; kc < 4; kc++)
                    mma16816(acc[bg][ng], afr[kc], bbv[ng][kc * 2], bbv[ng][kc * 2 + 1]);
        }
    }

    // epilogue: bf16 score store + fused rsum partial & tile max (fp32 accs)
    float lambda = __ldg(lam_p), tau = __ldg(tau_p);
#pragma unroll
    for (int bg = 0; bg < 2; bg++) {
        int bgi = wbh * 2 + bg;
        int brow = bgi * 16 + (lane >> 2);
        int ncol0 = n0 + wq * 32 + 2 * (lane & 3);
        float rs0 = 0.f, rs1 = 0.f, bm0 = -1e30f, bm1 = -1e30f;
#pragma unroll
        for (int ng = 0; ng < 4; ng++) {
            int n = ncol0 + ng * 8;
            if (n < N_) {
                __nv_bfloat162 pa = __float22bfloat162_rn(make_float2(acc[bg][ng][0], acc[bg][ng][1]));
                __nv_bfloat162 pb = __float22bfloat162_rn(make_float2(acc[bg][ng][2], acc[bg][ng][3]));
                *reinterpret_cast<uint32_t*>(&g_sb[(size_t)brow * N_ + n]) =
                    *reinterpret_cast<uint32_t*>(&pa);
                *reinterpret_cast<uint32_t*>(&g_sb[(size_t)(brow + 8) * N_ + n]) =
                    *reinterpret_cast<uint32_t*>(&pb);
                rs0 += rsum_term(acc[bg][ng][0], lambda, tau) + rsum_term(acc[bg][ng][1], lambda, tau);
                rs1 += rsum_term(acc[bg][ng][2], lambda, tau) + rsum_term(acc[bg][ng][3], lambda, tau);
                bm0 = fmaxf(bm0, fmaxf(acc[bg][ng][0], acc[bg][ng][1]));
                bm1 = fmaxf(bm1, fmaxf(acc[bg][ng][2], acc[bg][ng][3]));
            }
        }
#pragma unroll
        for (int off = 1; off <= 2; off <<= 1) {
            rs0 += __shfl_xor_sync(0xFFFFFFFFu, rs0, off);
            rs1 += __shfl_xor_sync(0xFFFFFFFFu, rs1, off);
            bm0 = fmaxf(bm0, __shfl_xor_sync(0xFFFFFFFFu, bm0, off));
            bm1 = fmaxf(bm1, __shfl_xor_sync(0xFFFFFFFFu, bm1, off));
        }
        if ((lane & 3) == 0) {
            s_rs[wq][brow] = rs0; s_rs[wq][brow + 8] = rs1;
            s_bm[wq][brow] = bm0; s_bm[wq][brow + 8] = bm1;
        }
    }
    __syncthreads();
    if (tid < 64) {
        float rtot = s_rs[0][tid] + s_rs[1][tid] + s_rs[2][tid] + s_rs[3][tid];
        float mtot = fmaxf(fmaxf(s_bm[0][tid], s_bm[1][tid]),
                           fmaxf(s_bm[2][tid], s_bm[3][tid]));
        g_rsp[tid * NT + blockIdx.x] = rtot;
        g_bmax[tid * NT + blockIdx.x] = mtot;
    }
}

// ---------------- K3: fused tail (512 threads, bf16 scores) ----------------
__global__ void __launch_bounds__(NTH) k_tail(const float* __restrict__ keys,
                                              const float* __restrict__ tau_p,
                                              const float* __restrict__ lam_p,
                                              const int* __restrict__ warm_p,
                                              int has_warm,
                                              float* __restrict__ out,
                                              int out_size) {
    __shared__ unsigned long long cand[CAP];       // 8 KB
    __shared__ unsigned long long top32[KMAX];
    __shared__ float sbm[NT];                      // tile maxima (3.1 KB)
    __shared__ int s_tiles[320];
    __shared__ float s_rs[16];
    __shared__ float s_T;
    __shared__ int s_ntile, s_ncand;
    int b = blockIdx.x;
    int tid = threadIdx.x;
    int wid = tid >> 5, lane = tid & 31;

    // Phase A: stage tile maxima to smem + rsum partial reduction
    float rsum = 0.f;
    for (int i = tid; i < NT; i += NTH) {
        sbm[i] = g_bmax[b * NT + i];
        rsum += g_rsp[b * NT + i];
    }
#pragma unroll
    for (int off = 16; off > 0; off >>= 1) rsum += __shfl_xor_sync(0xFFFFFFFFu, rsum, off);
    if (lane == 0) s_rs[wid] = rsum;
    if (tid == 0) { s_ntile = 0; s_ncand = 0; }
    __syncthreads();

    // Phase B: warp 0 register bisection (no block barriers inside)
    if (wid == 0) {
        float mv[25];
#pragma unroll
        for (int j = 0; j < 25; j++) {
            int idx = lane * 25 + j;
            mv[j] = (idx < NT) ? sbm[idx] : -2.f;
        }
        float lo = -1.001f, hi = 1.001f;
        for (int it = 0; it < 16; it++) {
            float mid = 0.5f * (lo + hi);
            int c = 0;
#pragma unroll
            for (int j = 0; j < 25; j++) c += (mv[j] >= mid);
#pragma unroll
            for (int off = 16; off > 0; off >>= 1) c += __shfl_xor_sync(0xFFFFFFFFu, c, off);
            if (c >= KMAX) lo = mid; else hi = mid;
        }
        if (lane == 0) s_T = lo - DELTA;
    }
    __syncthreads();
    float T = s_T;

    // Phase C: qualifying tile list
    for (int i = tid; i < NT; i += NTH)
        if (sbm[i] >= T) {
            int k = atomicAdd(&s_ntile, 1);
            if (k < 320) s_tiles[k] = i;
        }
    __syncthreads();
    int ntile = min(s_ntile, 320);

    // Phase D: collect candidates >= T from bf16 scores (uint4 = 8 scores)
    const __nv_bfloat16* srow = g_sb + (size_t)b * N_;
    int total = ntile * 128;
    for (int base = tid * 8; base < total; base += NTH * 8) {
        int tile = s_tiles[base >> 7];
        int n = tile * 128 + (base & 127);
        if (n + 7 < N_) {
            uint4 v = *reinterpret_cast<const uint4*>(srow + n);
            uint32_t w[4] = {v.x, v.y, v.z, v.w};
#pragma unroll
            for (int j = 0; j < 4; j++) {
                __nv_bfloat162 h = *reinterpret_cast<__nv_bfloat162*>(&w[j]);
                float f0 = __low2float(h), f1 = __high2float(h);
                if (f0 >= T) {
                    int idx = atomicAdd(&s_ncand, 1);
                    if (idx < CAP)
                        cand[idx] = ((unsigned long long)flipf(f0) << 32) |
                                    (unsigned long long)(0xFFFFFFFFu - (unsigned)(n + 2 * j));
                }
                if (f1 >= T) {
                    int idx = atomicAdd(&s_ncand, 1);
                    if (idx < CAP)
                        cand[idx] = ((unsigned long long)flipf(f1) << 32) |
                                    (unsigned long long)(0xFFFFFFFFu - (unsigned)(n + 2 * j + 1));
                }
            }
        } else {
#pragma unroll
            for (int j = 0; j < 8; j++) {
                int nn = n + j;
                if (nn < N_) {
                    float sv = __bfloat162float(srow[nn]);
                    if (sv >= T) {
                        int idx = atomicAdd(&s_ncand, 1);
                        if (idx < CAP)
                            cand[idx] = ((unsigned long long)flipf(sv) << 32) |
                                        (unsigned long long)(0xFFFFFFFFu - (unsigned)nn);
                    }
                }
            }
        }
    }
    __syncthreads();
    int cnt = min(s_ncand, CAP);

    // Phase E: exact rescore, 8 threads per candidate (one aspect each)
    for (int base = 0; base < cnt; base += NTH / 8) {
        int ci = base + (tid >> 3);
        int s = tid & 7;
        bool act = (ci < cnt);
        float contrib = 0.f;
        unsigned n = 0;
        if (act) {
            n = 0xFFFFFFFFu - (unsigned)(cand[ci] & 0xFFFFFFFFu);
            const float4* kp = reinterpret_cast<const float4*>(keys + ((size_t)s * N_ + n) * DK_);
            const float4* qp = reinterpret_cast<const float4*>(g_qhat + b * KTOT + s * 64);
            float ss = 0.f, dt = 0.f;
#pragma unroll
            for (int j = 0; j < 16; j++) {
                float4 kv = __ldg(kp + j);
                float4 qv = qp[j];
                ss += kv.x * kv.x + kv.y * kv.y + kv.z * kv.z + kv.w * kv.w;
                dt += kv.x * qv.x + kv.y * qv.y + kv.z * qv.z + kv.w * qv.w;
            }
            contrib = dt / (sqrtf(ss) + EPSF);
        }
        contrib += __shfl_xor_sync(0xFFFFFFFFu, contrib, 1);
        contrib += __shfl_xor_sync(0xFFFFFFFFu, contrib, 2);
        contrib += __shfl_xor_sync(0xFFFFFFFFu, contrib, 4);
        if (act && (tid & 7) == 0)
            cand[ci] = ((unsigned long long)flipf(contrib) << 32) |
                       (unsigned long long)(0xFFFFFFFFu - n);
    }
    __syncthreads();

    // Phase F: rank-based top-32 selection (keys unique -> exact ranks)
    for (int ci = tid; ci < cnt; ci += NTH) {
        unsigned long long k = cand[ci];
        int r = 0;
        for (int j = 0; j < cnt; j++) r += (cand[j] > k);
        if (r < KMAX) top32[r] = k;
    }
    __syncthreads();

    // Phase G: alpha + output (warp 0)
    if (wid == 0) {
        float lambda = __ldg(lam_p), tau = __ldg(tau_p);
        unsigned long long key = top32[lane];
        float myS = unflipf((unsigned)(key >> 32));
        int myN = (int)(0xFFFFFFFFu - (unsigned)(key & 0xFFFFFFFFu));

        int warm = has_warm ? __ldg(warm_p) : 0;
        float alpha;
        if (warm) {
            float smax = __shfl_sync(0xFFFFFFFFu, myS, 0);
            float e = expf(myS - smax);
            float den = e;
#pragma unroll
            for (int off = 16; off > 0; off >>= 1) den += __shfl_xor_sync(0xFFFFFFFFu, den, off);
            alpha = e / den;
        } else {
            float rs = 0.f;
#pragma unroll
            for (int i = 0; i < 16; i++) rs += s_rs[i];
            float x = lambda * (myS - tau);
            float gg = 1.f / (1.f + expf(-x));
            float r = gg * expf(myS);
            float nr = r / (rs + EPSF);
            float snr = nr;
#pragma unroll
            for (int off = 16; off > 0; off >>= 1) snr += __shfl_xor_sync(0xFFFFFFFFu, snr, off);
            alpha = nr / (snr + EPSF);
        }
        out[b * KMAX + lane] = alpha;
        if (out_size >= 2 * B_ * KMAX)
            out[B_ * KMAX + b * KMAX + lane] = (float)myN;
    }
}

// ---------------- host launch ----------------
extern "C" void kernel_launch(void* const* d_in, const int* in_sizes, int n_in,
                              void* d_out, int out_size) {
    const float* z    = (const float*)d_in[0];   // [64,2048]
    const float* keys = (const float*)d_in[1];   // [8,100000,64]
    const float* wq   = (const float*)d_in[2];   // [8,64,2048]
    const float* aw   = (const float*)d_in[3];   // [8]
    const float* tau  = (const float*)d_in[4];   // scalar
    const float* lam  = (const float*)d_in[5];   // scalar
    const int* warm   = (n_in > 6) ? (const int*)d_in[6] : nullptr;

    k_proj_partial<<<dim3(16, 8), 256>>>(z, wq);
    k_qfinish<<<B_, 256>>>(aw);

    cudaFuncSetAttribute(k_mma, cudaFuncAttributeMaxDynamicSharedMemorySize, SM_TOTAL);
    k_mma<<<NT, 256, SM_TOTAL>>>(keys, tau, lam);

    k_tail<<<B_, NTH>>>(keys, tau, lam, warm, warm != nullptr, (float*)d_out, out_size);
}

// round 14
// speedup vs baseline: 1.3912x; 1.0003x over previous
#include <cuda_runtime.h>
#include <cuda_bf16.h>
#include <math.h>
#include <stdint.h>

// Problem constants (fixed by setup_inputs)
#define B_   64
#define S_   8
#define DK_  64
#define DA_  2048
#define N_   100000
#define KTOT 512        // S_*DK_
#define KMAX 32
#define NT   782        // n-tiles of 128
#define CAP  1024       // candidate buffer per b (smem)
#define NTH  512        // k_tail threads
#define DELTA 4e-3f     // threshold safety margin (>> bf16 score+storage noise)
#define EPSF 1e-8f

// smem layout for k_mma (bytes) — single fp32 stage + double bf16 ks = 72KB
#define STG_STRIDE 288               // 256B fp32 row + split-pad (conflict-free)
#define STG_BUF (128 * STG_STRIDE)   // 36864 (single buffer)
#define KSROW 144                    // bf16 row: 128B + 16 pad
#define KSBUF (128 * KSROW)          // 18432
#define SM_KS  STG_BUF               // 36864
#define SM_TOTAL (SM_KS + 2 * KSBUF) // 73728 -> 3 CTAs/SM (221KB smem)

// ---------------- device scratch ----------------
__device__ float g_qpart[16 * B_ * KTOT];
__device__ float g_qhat[B_ * KTOT];               // fp32 q̂ (exact rescore)
__device__ uint4 g_qfrag[128 * 32];               // mma A fragments (64 KB)
__device__ __nv_bfloat16 g_sb[(size_t)B_ * N_];   // approx scores bf16 (12.8 MB)
__device__ float g_rsp[B_ * NT];                  // rsum partials per (b,tile)
__device__ float g_bmax[B_ * NT];                 // per-(b,tile) max (fp32)

// ================= helpers =================
__device__ __forceinline__ uint32_t smem_u32(const void* p) {
    uint32_t a;
    asm("{ .reg .u64 t; cvta.to.shared.u64 t, %1; cvt.u32.u64 %0, t; }" : "=r"(a) : "l"(p));
    return a;
}
__device__ __forceinline__ void cp_async16(uint32_t dst, const void* src) {
    asm volatile("cp.async.cg.shared.global [%0], [%1], 16;" :: "r"(dst), "l"(src));
}
#define CP_COMMIT() asm volatile("cp.async.commit_group;" ::: "memory")
#define CP_WAIT0()  asm volatile("cp.async.wait_group 0;" ::: "memory")
__device__ __forceinline__ void ldsm_x4(uint32_t& r0, uint32_t& r1, uint32_t& r2,
                                        uint32_t& r3, uint32_t addr) {
    asm volatile("ldmatrix.sync.aligned.m8n8.x4.shared.b16 {%0,%1,%2,%3}, [%4];"
                 : "=r"(r0), "=r"(r1), "=r"(r2), "=r"(r3) : "r"(addr));
}
__device__ __forceinline__ void mma16816(float* c, const uint32_t* a,
                                         uint32_t b0, uint32_t b1) {
    asm volatile(
        "mma.sync.aligned.m16n8k16.row.col.f32.bf16.bf16.f32 "
        "{%0,%1,%2,%3}, {%4,%5,%6,%7}, {%8,%9}, {%0,%1,%2,%3};"
        : "+f"(c[0]), "+f"(c[1]), "+f"(c[2]), "+f"(c[3])
        : "r"(a[0]), "r"(a[1]), "r"(a[2]), "r"(a[3]), "r"(b0), "r"(b1));
}
__device__ __forceinline__ unsigned flipf(float f) {
    unsigned u = __float_as_uint(f);
    return (u & 0x80000000u) ? ~u : (u | 0x80000000u);
}
__device__ __forceinline__ float unflipf(unsigned u) {
    return __uint_as_float((u & 0x80000000u) ? (u & 0x7FFFFFFFu) : ~u);
}
// 0-MUFU sigmoid(lambda(s-tau)) * exp(s) approximation (rsum only; ~0.1% acc)
__device__ __forceinline__ float rsum_term(float s, float lambda, float tau) {
    float e = 1.f + s * (1.f + s * (0.5f + s * (0.16666667f + s * (0.041666667f + s * 0.0083333333f))));
    float x = lambda * (s - tau);
    float ax = fabsf(x);
    float t;
    if (ax >= 4.5f) {
        t = 1.f;
    } else {
        float y = 0.5f * ax, y2 = y * y;
        float num = y * (27.f + y2);
        float den = fmaf(9.f, y2, 27.f);
        float rc = fmaf(den, -5.10e-4f, 0.05081f);
        rc = rc * (2.f - den * rc);
        rc = rc * (2.f - den * rc);
        t = fminf(num * rc, 1.f);
    }
    float g = fmaf(copysignf(t, x), 0.5f, 0.5f);
    return g * e;
}

// ---------------- K1a: query projection partial GEMM ----------------
__global__ void __launch_bounds__(256) k_proj_partial(const float* __restrict__ z,
                                                      const float* __restrict__ wq) {
    __shared__ float zt[64][33];
    __shared__ float wt[64][33];
    int tid = threadIdx.x;
    int tx = tid & 15, ty = tid >> 4;
    int a_base = blockIdx.x * 128;
    int sk_base = blockIdx.y * 64;
    float acc[4][4] = {};
    for (int t = 0; t < 4; t++) {
        int a0 = a_base + t * 32;
        for (int idx = tid; idx < 64 * 32; idx += 256) {
            int r = idx >> 5, c = idx & 31;
            zt[r][c] = z[r * DA_ + a0 + c];
            wt[r][c] = wq[(size_t)(sk_base + r) * DA_ + a0 + c];
        }
        __syncthreads();
#pragma unroll
        for (int a = 0; a < 32; a++) {
            float zv[4], wv[4];
#pragma unroll
            for (int i = 0; i < 4; i++) zv[i] = zt[4 * ty + i][a];
#pragma unroll
            for (int j = 0; j < 4; j++) wv[j] = wt[4 * tx + j][a];
#pragma unroll
            for (int i = 0; i < 4; i++)
#pragma unroll
                for (int j = 0; j < 4; j++) acc[i][j] += zv[i] * wv[j];
        }
        __syncthreads();
    }
#pragma unroll
    for (int i = 0; i < 4; i++)
#pragma unroll
        for (int j = 0; j < 4; j++)
            g_qpart[blockIdx.x * (B_ * KTOT) + (4 * ty + i) * KTOT + sk_base + 4 * tx + j] = acc[i][j];
}

// ---------------- K1b: reduce + normalize + softmax + emit fragments -------
__global__ void __launch_bounds__(256) k_qfinish(const float* __restrict__ aw) {
    __shared__ __nv_bfloat16 shq[8][64];
    int b = blockIdx.x;
    int tid = threadIdx.x;
    int s = tid >> 5, lane = tid & 31;
    int idx0 = b * KTOT + s * 64 + lane;
    int idx1 = idx0 + 32;

    float q0 = 0.f, q1 = 0.f;
#pragma unroll
    for (int p = 0; p < 16; p++) {
        q0 += g_qpart[p * (B_ * KTOT) + idx0];
        q1 += g_qpart[p * (B_ * KTOT) + idx1];
    }
    float ss = q0 * q0 + q1 * q1;
#pragma unroll
    for (int off = 16; off > 0; off >>= 1) ss += __shfl_xor_sync(0xFFFFFFFFu, ss, off);
    float m = aw[0];
#pragma unroll
    for (int i = 1; i < 8; i++) m = fmaxf(m, aw[i]);
    float den = 0.f, es = 0.f;
#pragma unroll
    for (int i = 0; i < 8; i++) {
        float e = expf(aw[i] - m);
        den += e;
        if (i == s) es = e;
    }
    float scale = (es / den) / (sqrtf(ss) + EPSF);
    float h0 = q0 * scale, h1 = q1 * scale;
    g_qhat[idx0] = h0;
    g_qhat[idx1] = h1;
    shq[s][lane] = __float2bfloat16(h0);
    shq[s][lane + 32] = __float2bfloat16(h1);
    __syncwarp();

    int kc = lane >> 3, t = (lane >> 1) & 3, h = lane & 1;
    int col = kc * 16 + h * 8 + 2 * t;
    __nv_bfloat162 pr = __halves2bfloat162(*(__nv_bfloat16*)&shq[s][col],
                                           *(__nv_bfloat16*)&shq[s][col + 1]);
    uint32_t val = *reinterpret_cast<uint32_t*>(&pr);
    int gp = b & 15;
    int frag = (s * 4 + kc) * 4 + (b >> 4);
    int comp = 2 * h + (gp >= 8 ? 1 : 0);
    int lanep = (gp & 7) * 4 + t;
    reinterpret_cast<uint32_t*>(g_qfrag)[frag * 128 + lanep * 4 + comp] = val;
}

// ---------------- K2: bf16 HMMA score GEMM, 3 CTAs/SM, depth-1 staging -----
__global__ void __launch_bounds__(256, 3) k_mma(const float* __restrict__ keys,
                                                const float* __restrict__ tau_p,
                                                const float* __restrict__ lam_p) {
    extern __shared__ char smem[];
    __shared__ float s_rs[4][64];
    __shared__ float s_bm[4][64];
    uint32_t sb = smem_u32(smem);
    int tid = threadIdx.x;
    int wid = tid >> 5, lane = tid & 31;
    int wbh = wid & 1, wq = wid >> 1;
    int n0 = blockIdx.x * 128;

    int r = tid >> 1, hf = tid & 1;
    int nrow = n0 + r;
    if (nrow >= N_) nrow = N_ - 1;
    const float* krow0 = keys + (size_t)nrow * DK_ + hf * 32;
    uint32_t mystg = sb + r * STG_STRIDE + hf * 144;

    // prologue: stage aspect 0
#pragma unroll
    for (int c = 0; c < 8; c++) cp_async16(mystg + c * 16, krow0 + c * 4);
    CP_COMMIT();

    float acc[2][4][4] = {};
    int b_rowlane = wq * 32 + (lane & 7);
    int b_kof = (lane >> 3) * 8;

    for (int s = 0; s < S_; s++) {
        CP_WAIT0();
        __syncthreads();

        // LDS fp32 keys, norm, convert+STS bf16 into ks[s&1]
        float4 v[8];
        const float4* sp = reinterpret_cast<const float4*>(smem + r * STG_STRIDE + hf * 144);
#pragma unroll
        for (int j = 0; j < 8; j++) v[j] = sp[j];
        float ssv = 0.f;
#pragma unroll
        for (int j = 0; j < 8; j++)
            ssv += v[j].x * v[j].x + v[j].y * v[j].y + v[j].z * v[j].z + v[j].w * v[j].w;
        ssv += __shfl_xor_sync(0xFFFFFFFFu, ssv, 1);
        float inv = rsqrtf(ssv);

        char* rowp = smem + SM_KS + (s & 1) * KSBUF + r * KSROW + hf * 64;
#pragma unroll
        for (int j = 0; j < 4; j++) {
            float4 a = v[2 * j], b4 = v[2 * j + 1];
            __nv_bfloat162 p0 = __float22bfloat162_rn(make_float2(a.x * inv, a.y * inv));
            __nv_bfloat162 p1 = __float22bfloat162_rn(make_float2(a.z * inv, a.w * inv));
            __nv_bfloat162 p2 = __float22bfloat162_rn(make_float2(b4.x * inv, b4.y * inv));
            __nv_bfloat162 p3 = __float22bfloat162_rn(make_float2(b4.z * inv, b4.w * inv));
            uint4 pk;
            pk.x = *reinterpret_cast<uint32_t*>(&p0);
            pk.y = *reinterpret_cast<uint32_t*>(&p1);
            pk.z = *reinterpret_cast<uint32_t*>(&p2);
            pk.w = *reinterpret_cast<uint32_t*>(&p3);
            *reinterpret_cast<uint4*>(rowp + j * 16) = pk;
        }
        __syncthreads();   // stage consumed + ks[s&1] ready

        // prefetch aspect s+1 into the (now free) single stage buffer
        if (s + 1 < S_) {
            const float* src = krow0 + (size_t)(s + 1) * N_ * DK_;
#pragma unroll
            for (int c = 0; c < 8; c++) cp_async16(mystg + c * 16, src + c * 4);
            CP_COMMIT();
        }

        // A fragments for both 16-row b-groups (live whole aspect: 32 regs)
        uint32_t afr[2][4][4];
#pragma unroll
        for (int bg = 0; bg < 2; bg++) {
            int bgi = wbh * 2 + bg;
#pragma unroll
            for (int kc = 0; kc < 4; kc++) {
                uint4 qf = __ldg(&g_qfrag[((s * 4 + kc) * 4 + bgi) * 32 + lane]);
                afr[bg][kc][0] = qf.x; afr[bg][kc][1] = qf.y;
                afr[bg][kc][2] = qf.z; afr[bg][kc][3] = qf.w;
            }
        }
        // B fragments one n-group at a time (8 transient regs)
        uint32_t bufo = SM_KS + (s & 1) * KSBUF;
#pragma unroll
        for (int ng = 0; ng < 4; ng++) {
            uint32_t baddr = sb + bufo + (b_rowlane + ng * 8) * KSROW + b_kof * 2;
            uint32_t bb[8];
            ldsm_x4(bb[0], bb[1], bb[2], bb[3], baddr);
            ldsm_x4(bb[4], bb[5], bb[6], bb[7], baddr + 64);
#pragma unroll
            for (int bg = 0; bg < 2; bg++)
#pragma unroll
                for (int kc = 0; kc < 4; kc++)
                    mma16816(acc[bg][ng], afr[bg][kc], bb[kc * 2], bb[kc * 2 + 1]);
        }
    }

    // epilogue: bf16 score store + fused rsum partial & tile max (fp32 accs)
    float lambda = __ldg(lam_p), tau = __ldg(tau_p);
#pragma unroll
    for (int bg = 0; bg < 2; bg++) {
        int bgi = wbh * 2 + bg;
        int brow = bgi * 16 + (lane >> 2);
        int ncol0 = n0 + wq * 32 + 2 * (lane & 3);
        float rs0 = 0.f, rs1 = 0.f, bm0 = -1e30f, bm1 = -1e30f;
#pragma unroll
        for (int ng = 0; ng < 4; ng++) {
            int n = ncol0 + ng * 8;
            if (n < N_) {
                __nv_bfloat162 pa = __float22bfloat162_rn(make_float2(acc[bg][ng][0], acc[bg][ng][1]));
                __nv_bfloat162 pb = __float22bfloat162_rn(make_float2(acc[bg][ng][2], acc[bg][ng][3]));
                *reinterpret_cast<uint32_t*>(&g_sb[(size_t)brow * N_ + n]) =
                    *reinterpret_cast<uint32_t*>(&pa);
                *reinterpret_cast<uint32_t*>(&g_sb[(size_t)(brow + 8) * N_ + n]) =
                    *reinterpret_cast<uint32_t*>(&pb);
                rs0 += rsum_term(acc[bg][ng][0], lambda, tau) + rsum_term(acc[bg][ng][1], lambda, tau);
                rs1 += rsum_term(acc[bg][ng][2], lambda, tau) + rsum_term(acc[bg][ng][3], lambda, tau);
                bm0 = fmaxf(bm0, fmaxf(acc[bg][ng][0], acc[bg][ng][1]));
                bm1 = fmaxf(bm1, fmaxf(acc[bg][ng][2], acc[bg][ng][3]));
            }
        }
#pragma unroll
        for (int off = 1; off <= 2; off <<= 1) {
            rs0 += __shfl_xor_sync(0xFFFFFFFFu, rs0, off);
            rs1 += __shfl_xor_sync(0xFFFFFFFFu, rs1, off);
            bm0 = fmaxf(bm0, __shfl_xor_sync(0xFFFFFFFFu, bm0, off));
            bm1 = fmaxf(bm1, __shfl_xor_sync(0xFFFFFFFFu, bm1, off));
        }
        if ((lane & 3) == 0) {
            s_rs[wq][brow] = rs0; s_rs[wq][brow + 8] = rs1;
            s_bm[wq][brow] = bm0; s_bm[wq][brow + 8] = bm1;
        }
    }
    __syncthreads();
    if (tid < 64) {
        float rtot = s_rs[0][tid] + s_rs[1][tid] + s_rs[2][tid] + s_rs[3][tid];
        float mtot = fmaxf(fmaxf(s_bm[0][tid], s_bm[1][tid]),
                           fmaxf(s_bm[2][tid], s_bm[3][tid]));
        g_rsp[tid * NT + blockIdx.x] = rtot;
        g_bmax[tid * NT + blockIdx.x] = mtot;
    }
}

// ---------------- K3: fused tail (512 threads, bf16 scores) ----------------
__global__ void __launch_bounds__(NTH) k_tail(const float* __restrict__ keys,
                                              const float* __restrict__ tau_p,
                                              const float* __restrict__ lam_p,
                                              const int* __restrict__ warm_p,
                                              int has_warm,
                                              float* __restrict__ out,
                                              int out_size) {
    __shared__ unsigned long long cand[CAP];       // 8 KB
    __shared__ unsigned long long top32[KMAX];
    __shared__ float sbm[NT];                      // tile maxima (3.1 KB)
    __shared__ int s_tiles[320];
    __shared__ float s_rs[16];
    __shared__ float s_T;
    __shared__ int s_ntile, s_ncand;
    int b = blockIdx.x;
    int tid = threadIdx.x;
    int wid = tid >> 5, lane = tid & 31;

    // Phase A: stage tile maxima to smem + rsum partial reduction
    float rsum = 0.f;
    for (int i = tid; i < NT; i += NTH) {
        sbm[i] = g_bmax[b * NT + i];
        rsum += g_rsp[b * NT + i];
    }
#pragma unroll
    for (int off = 16; off > 0; off >>= 1) rsum += __shfl_xor_sync(0xFFFFFFFFu, rsum, off);
    if (lane == 0) s_rs[wid] = rsum;
    if (tid == 0) { s_ntile = 0; s_ncand = 0; }
    __syncthreads();

    // Phase B: warp 0 register bisection (no block barriers inside)
    if (wid == 0) {
        float mv[25];
#pragma unroll
        for (int j = 0; j < 25; j++) {
            int idx = lane * 25 + j;
            mv[j] = (idx < NT) ? sbm[idx] : -2.f;
        }
        float lo = -1.001f, hi = 1.001f;
        for (int it = 0; it < 16; it++) {
            float mid = 0.5f * (lo + hi);
            int c = 0;
#pragma unroll
            for (int j = 0; j < 25; j++) c += (mv[j] >= mid);
#pragma unroll
            for (int off = 16; off > 0; off >>= 1) c += __shfl_xor_sync(0xFFFFFFFFu, c, off);
            if (c >= KMAX) lo = mid; else hi = mid;
        }
        if (lane == 0) s_T = lo - DELTA;
    }
    __syncthreads();
    float T = s_T;

    // Phase C: qualifying tile list
    for (int i = tid; i < NT; i += NTH)
        if (sbm[i] >= T) {
            int k = atomicAdd(&s_ntile, 1);
            if (k < 320) s_tiles[k] = i;
        }
    __syncthreads();
    int ntile = min(s_ntile, 320);

    // Phase D: collect candidates >= T from bf16 scores (uint4 = 8 scores)
    const __nv_bfloat16* srow = g_sb + (size_t)b * N_;
    int total = ntile * 128;
    for (int base = tid * 8; base < total; base += NTH * 8) {
        int tile = s_tiles[base >> 7];
        int n = tile * 128 + (base & 127);
        if (n + 7 < N_) {
            uint4 v = *reinterpret_cast<const uint4*>(srow + n);
            uint32_t w[4] = {v.x, v.y, v.z, v.w};
#pragma unroll
            for (int j = 0; j < 4; j++) {
                __nv_bfloat162 h = *reinterpret_cast<__nv_bfloat162*>(&w[j]);
                float f0 = __low2float(h), f1 = __high2float(h);
                if (f0 >= T) {
                    int idx = atomicAdd(&s_ncand, 1);
                    if (idx < CAP)
                        cand[idx] = ((unsigned long long)flipf(f0) << 32) |
                                    (unsigned long long)(0xFFFFFFFFu - (unsigned)(n + 2 * j));
                }
                if (f1 >= T) {
                    int idx = atomicAdd(&s_ncand, 1);
                    if (idx < CAP)
                        cand[idx] = ((unsigned long long)flipf(f1) << 32) |
                                    (unsigned long long)(0xFFFFFFFFu - (unsigned)(n + 2 * j + 1));
                }
            }
        } else {
#pragma unroll
            for (int j = 0; j < 8; j++) {
                int nn = n + j;
                if (nn < N_) {
                    float sv = __bfloat162float(srow[nn]);
                    if (sv >= T) {
                        int idx = atomicAdd(&s_ncand, 1);
                        if (idx < CAP)
                            cand[idx] = ((unsigned long long)flipf(sv) << 32) |
                                        (unsigned long long)(0xFFFFFFFFu - (unsigned)nn);
                    }
                }
            }
        }
    }
    __syncthreads();
    int cnt = min(s_ncand, CAP);

    // Phase E: exact rescore, 8 threads per candidate (one aspect each)
    for (int base = 0; base < cnt; base += NTH / 8) {
        int ci = base + (tid >> 3);
        int s = tid & 7;
        bool act = (ci < cnt);
        float contrib = 0.f;
        unsigned n = 0;
        if (act) {
            n = 0xFFFFFFFFu - (unsigned)(cand[ci] & 0xFFFFFFFFu);
            const float4* kp = reinterpret_cast<const float4*>(keys + ((size_t)s * N_ + n) * DK_);
            const float4* qp = reinterpret_cast<const float4*>(g_qhat + b * KTOT + s * 64);
            float ss = 0.f, dt = 0.f;
#pragma unroll
            for (int j = 0; j < 16; j++) {
                float4 kv = __ldg(kp + j);
                float4 qv = qp[j];
                ss += kv.x * kv.x + kv.y * kv.y + kv.z * kv.z + kv.w * kv.w;
                dt += kv.x * qv.x + kv.y * qv.y + kv.z * qv.z + kv.w * qv.w;
            }
            contrib = dt / (sqrtf(ss) + EPSF);
        }
        contrib += __shfl_xor_sync(0xFFFFFFFFu, contrib, 1);
        contrib += __shfl_xor_sync(0xFFFFFFFFu, contrib, 2);
        contrib += __shfl_xor_sync(0xFFFFFFFFu, contrib, 4);
        if (act && (tid & 7) == 0)
            cand[ci] = ((unsigned long long)flipf(contrib) << 32) |
                       (unsigned long long)(0xFFFFFFFFu - n);
    }
    __syncthreads();

    // Phase F: rank-based top-32 selection (keys unique -> exact ranks)
    for (int ci = tid; ci < cnt; ci += NTH) {
        unsigned long long k = cand[ci];
        int r = 0;
        for (int j = 0; j < cnt; j++) r += (cand[j] > k);
        if (r < KMAX) top32[r] = k;
    }
    __syncthreads();

    // Phase G: alpha + output (warp 0)
    if (wid == 0) {
        float lambda = __ldg(lam_p), tau = __ldg(tau_p);
        unsigned long long key = top32[lane];
        float myS = unflipf((unsigned)(key >> 32));
        int myN = (int)(0xFFFFFFFFu - (unsigned)(key & 0xFFFFFFFFu));

        int warm = has_warm ? __ldg(warm_p) : 0;
        float alpha;
        if (warm) {
            float smax = __shfl_sync(0xFFFFFFFFu, myS, 0);
            float e = expf(myS - smax);
            float den = e;
#pragma unroll
            for (int off = 16; off > 0; off >>= 1) den += __shfl_xor_sync(0xFFFFFFFFu, den, off);
            alpha = e / den;
        } else {
            float rs = 0.f;
#pragma unroll
            for (int i = 0; i < 16; i++) rs += s_rs[i];
            float x = lambda * (myS - tau);
            float gg = 1.f / (1.f + expf(-x));
            float r = gg * expf(myS);
            float nr = r / (rs + EPSF);
            float snr = nr;
#pragma unroll
            for (int off = 16; off > 0; off >>= 1) snr += __shfl_xor_sync(0xFFFFFFFFu, snr, off);
            alpha = nr / (snr + EPSF);
        }
        out[b * KMAX + lane] = alpha;
        if (out_size >= 2 * B_ * KMAX)
            out[B_ * KMAX + b * KMAX + lane] = (float)myN;
    }
}

// ---------------- host launch ----------------
extern "C" void kernel_launch(void* const* d_in, const int* in_sizes, int n_in,
                              void* d_out, int out_size) {
    const float* z    = (const float*)d_in[0];   // [64,2048]
    const float* keys = (const float*)d_in[1];   // [8,100000,64]
    const float* wq   = (const float*)d_in[2];   // [8,64,2048]
    const float* aw   = (const float*)d_in[3];   // [8]
    const float* tau  = (const float*)d_in[4];   // scalar
    const float* lam  = (const float*)d_in[5];   // scalar
    const int* warm   = (n_in > 6) ? (const int*)d_in[6] : nullptr;

    k_proj_partial<<<dim3(16, 8), 256>>>(z, wq);
    k_qfinish<<<B_, 256>>>(aw);

    cudaFuncSetAttribute(k_mma, cudaFuncAttributeMaxDynamicSharedMemorySize, SM_TOTAL);
    k_mma<<<NT, 256, SM_TOTAL>>>(keys, tau, lam);

    k_tail<<<B_, NTH>>>(keys, tau, lam, warm, warm != nullptr, (float*)d_out, out_size);
}